// round 6
// baseline (speedup 1.0000x reference)
#include <cuda_runtime.h>
#include <math.h>
#include <stdint.h>

#define BB   2
#define TT   2048
#define CC   1024
#define HH   16
#define HD   64
#define MROWS (BB*TT)        // 4096
#define N_QKV (3*CC)         // 3072

// ---------------------------------------------------------------------------
// Scratch (device globals)
// ---------------------------------------------------------------------------
__device__ __align__(1024) float g_q[BB*HH*TT*HD];   // [B,H,T,HD]  tf32
__device__ __align__(1024) float g_k[BB*HH*TT*HD];   // [B,H,T,HD]  tf32
__device__ __align__(1024) float g_v[BB*HH*TT*HD];   // [B,H,HD,T]  tf32 (TRANSPOSED)
__device__ __align__(1024) float g_y[MROWS*CC];      // attn out, PERMUTED tf32
__device__ __align__(1024) float g_xp[MROWS*CC];     // x, PERMUTED tf32
__device__ __align__(1024) float g_wtq[N_QKV*CC];    // Wqkv^T, PERMUTED tf32
__device__ __align__(1024) float g_wtp[CC*CC];       // Wproj^T, PERMUTED tf32

// ---------------------------------------------------------------------------
// Helpers
// ---------------------------------------------------------------------------
__device__ __forceinline__ float to_tf32(float x) {
    float r;
    asm("cvt.rna.tf32.f32 %0, %1;" : "=f"(r) : "f"(x));
    return r;
}

__device__ __forceinline__ uint32_t s2u(const void* p) {
    uint32_t a;
    asm("{ .reg .u64 t; cvta.to.shared.u64 t, %1; cvt.u32.u64 %0, t; }"
        : "=r"(a) : "l"(p));
    return a;
}

__device__ __forceinline__ void cp_async16(uint32_t dst, const float* src) {
    asm volatile("cp.async.cg.shared.global [%0], [%1], 16;"
                 :: "r"(dst), "l"(src) : "memory");
}

__device__ __forceinline__ float f4e(const float4& v, int i) {
    return i == 0 ? v.x : (i == 1 ? v.y : (i == 2 ? v.z : v.w));
}

__device__ __forceinline__ void mma_tf32(float d[4], float a0, float a1,
                                         float a2, float a3, float b0, float b1)
{
    asm volatile(
        "mma.sync.aligned.m16n8k8.row.col.f32.tf32.tf32.f32 "
        "{%0,%1,%2,%3}, {%4,%5,%6,%7}, {%8,%9}, {%0,%1,%2,%3};"
        : "+f"(d[0]), "+f"(d[1]), "+f"(d[2]), "+f"(d[3])
        : "r"(__float_as_uint(a0)), "r"(__float_as_uint(a1)),
          "r"(__float_as_uint(a2)), "r"(__float_as_uint(a3)),
          "r"(__float_as_uint(b0)), "r"(__float_as_uint(b1)));
}

// ---------------------------------------------------------------------------
// Prep kernels
// ---------------------------------------------------------------------------
__global__ void prep_A(const float* __restrict__ in, float* __restrict__ out,
                       int total4, int K)
{
    int idx = blockIdx.x * 256 + threadIdx.x;
    if (idx >= total4) return;
    int row = idx / (K / 4);
    int k   = (idx % (K / 4)) * 4;
    float4 v = *(const float4*)(in + (size_t)row * K + k);
    int kb = k & ~31;
    int q  = (k & 31) >> 2;
    float* o = out + (size_t)row * K + kb;
    o[q]      = to_tf32(v.x);
    o[8 + q]  = to_tf32(v.y);
    o[16 + q] = to_tf32(v.z);
    o[24 + q] = to_tf32(v.w);
}

__global__ void transpose_perm(const float* __restrict__ in,
                               float* __restrict__ out, int R, int C)
{
    __shared__ float t[32][33];
    int c0 = blockIdx.x * 32, r0 = blockIdx.y * 32;
    int x = threadIdx.x, y = threadIdx.y;
#pragma unroll
    for (int i = 0; i < 32; i += 8)
        t[y + i][x] = in[(size_t)(r0 + y + i) * C + c0 + x];
    __syncthreads();
    int xp = (x & 3) * 8 + (x >> 2);
#pragma unroll
    for (int i = 0; i < 32; i += 8)
        out[(size_t)(c0 + y + i) * R + r0 + xp] = to_tf32(t[x][y + i]);
}

// ---------------------------------------------------------------------------
// TF32 mma.sync GEMM. Single-sync multistage pipeline, 2 CTAs/SM.
// ---------------------------------------------------------------------------
#define GSTAGES 3
#define KB      32
#define APAD    36
#define TILE_F  (128*APAD)
#define GEMM_SMEM (GSTAGES*2*TILE_F*4)

__device__ __forceinline__ void g_load_stage(uint32_t sbase, int s,
                                             const float* Ag, const float* Bg,
                                             int k0, int tid)
{
    uint32_t base = sbase + (uint32_t)s * 2 * TILE_F * 4;
#pragma unroll
    for (int i = 0; i < 4; i++) {
        int f = tid + i * 256;
        int row = f >> 3, c = f & 7;
        cp_async16(base + row * (APAD * 4) + c * 16,
                   Ag + (size_t)row * CC + k0 + c * 4);
        cp_async16(base + TILE_F * 4 + row * (APAD * 4) + c * 16,
                   Bg + (size_t)row * CC + k0 + c * 4);
    }
    asm volatile("cp.async.commit_group;" ::: "memory");
}

template <int MODE>
__global__ __launch_bounds__(256, 2)
void mma_gemm(const float* __restrict__ A, const float* __restrict__ Bt,
              const float* __restrict__ bias, float* __restrict__ Cout, int Nn)
{
    extern __shared__ __align__(16) float sm[];
    const uint32_t sbase = s2u(sm);
    const int tid  = threadIdx.x;
    const int lane = tid & 31;
    const int wid  = tid >> 5;
    const int wm   = wid & 3;
    const int wn   = wid >> 2;
    const int r    = lane >> 2;
    const int l4   = lane & 3;
    const int m0 = blockIdx.y * 128;
    const int n0 = blockIdx.x * 128;

    const float* Ag = A + (size_t)m0 * CC;
    const float* Bg = Bt + (size_t)n0 * CC;

    float acc[2][8][4];
#pragma unroll
    for (int mt = 0; mt < 2; mt++)
#pragma unroll
        for (int nt = 0; nt < 8; nt++)
#pragma unroll
            for (int j = 0; j < 4; j++) acc[mt][nt][j] = 0.0f;

    const int NIT = CC / KB;   // 32

    // Prologue: fill S-1 stages (blocks 0..S-2, block b -> buffer b%S)
#pragma unroll
    for (int s = 0; s < GSTAGES - 1; s++)
        g_load_stage(sbase, s, Ag, Bg, s * KB, tid);

    for (int it = 0; it < NIT; it++) {
        // Block `it` ready when at most S-2 newer groups remain pending.
        if (it < NIT - 1)
            asm volatile("cp.async.wait_group %0;" :: "n"(GSTAGES - 2) : "memory");
        else
            asm volatile("cp.async.wait_group 0;" ::: "memory");
        __syncthreads();   // also: buffer (it-1)%S fully consumed by all warps

        // Issue loads for block it+S-1 into buffer (it+S-1)%S == (it-1)%S
        if (it + GSTAGES - 1 < NIT)
            g_load_stage(sbase, (it + GSTAGES - 1) % GSTAGES, Ag, Bg,
                         (it + GSTAGES - 1) * KB, tid);

        const float* As = sm + (size_t)(it % GSTAGES) * 2 * TILE_F;
        const float* Bs = As + TILE_F;

        float4 af[2][2][2];
#pragma unroll
        for (int mt = 0; mt < 2; mt++) {
            const float* ap = As + (wm * 32 + mt * 16 + r) * APAD + l4 * 8;
            af[mt][0][0] = *(const float4*)ap;
            af[mt][0][1] = *(const float4*)(ap + 4);
            ap += 8 * APAD;
            af[mt][1][0] = *(const float4*)ap;
            af[mt][1][1] = *(const float4*)(ap + 4);
        }
        float4 bfr[8][2];
#pragma unroll
        for (int nt = 0; nt < 8; nt++) {
            const float* bp = Bs + (wn * 64 + nt * 8 + r) * APAD + l4 * 8;
            bfr[nt][0] = *(const float4*)bp;
            bfr[nt][1] = *(const float4*)(bp + 4);
        }

#pragma unroll
        for (int g = 0; g < 4; g++) {
            const int hi = g >> 1, e0 = (g & 1) * 2, e1 = e0 + 1;
#pragma unroll
            for (int mt = 0; mt < 2; mt++) {
                float a0 = f4e(af[mt][0][hi], e0);
                float a1 = f4e(af[mt][1][hi], e0);
                float a2 = f4e(af[mt][0][hi], e1);
                float a3 = f4e(af[mt][1][hi], e1);
#pragma unroll
                for (int nt = 0; nt < 8; nt++) {
                    float b0 = f4e(bfr[nt][hi], e0);
                    float b1 = f4e(bfr[nt][hi], e1);
                    mma_tf32(acc[mt][nt], a0, a1, a2, a3, b0, b1);
                }
            }
        }
    }

#pragma unroll
    for (int mt = 0; mt < 2; mt++) {
#pragma unroll
        for (int nt = 0; nt < 8; nt++) {
            const int row = m0 + wm * 32 + mt * 16 + r;
            const int c   = n0 + wn * 64 + nt * 8 + 2 * l4;
            const float b0v = __ldg(bias + c);
            const float b1v = __ldg(bias + c + 1);
            float v00 = acc[mt][nt][0] + b0v, v01 = acc[mt][nt][1] + b1v;
            float v10 = acc[mt][nt][2] + b0v, v11 = acc[mt][nt][3] + b1v;
            if (MODE == 0) {
                const int sec = c >> 10;
                const int cs = c & 1023, h = cs >> 6, d0 = cs & 63;
                const int b  = row >> 11;
                const int t0 = row & 2047;
                const int t1 = (row + 8) & 2047;
                if (sec == 2) {
                    float* vb = g_v + ((size_t)(b * HH + h) * HD) * TT;
                    vb[(size_t)d0 * TT + t0]       = to_tf32(v00);
                    vb[(size_t)(d0 + 1) * TT + t0] = to_tf32(v01);
                    vb[(size_t)d0 * TT + t1]       = to_tf32(v10);
                    vb[(size_t)(d0 + 1) * TT + t1] = to_tf32(v11);
                } else {
                    float* basep = (sec == 0) ? g_q : g_k;
                    float* p0 = basep + (((size_t)(b * HH + h) * TT + t0) * HD + d0);
                    float* p1 = basep + (((size_t)(b * HH + h) * TT + t1) * HD + d0);
                    *(float2*)p0 = make_float2(to_tf32(v00), to_tf32(v01));
                    *(float2*)p1 = make_float2(to_tf32(v10), to_tf32(v11));
                }
            } else {
                *(float2*)(Cout + (size_t)row * Nn + c)       = make_float2(v00, v01);
                *(float2*)(Cout + (size_t)(row + 8) * Nn + c) = make_float2(v10, v11);
            }
        }
    }
}

// ---------------------------------------------------------------------------
// Flash attention on tf32 mma.sync — double-buffered K/V with LDG prefetch,
// one __syncthreads per k-tile.
// smem: Ksm[2][64][72], VTs[2][64][72], Ps[128][72]
// ---------------------------------------------------------------------------
#define AT_PAD  72
#define AT_SMEM ((2*64*AT_PAD*2 + 128*AT_PAD)*4)

__global__ __launch_bounds__(256, 1)
void attn_mma(float* __restrict__ Yg)
{
    extern __shared__ __align__(16) float smf[];
    float* Kb[2] = { smf,                smf + 64 * AT_PAD };
    float* Vb[2] = { smf + 2*64*AT_PAD,  smf + 3*64*AT_PAD };
    float* Ps    = smf + 4 * 64 * AT_PAD;   // [128][72]

    const int tid  = threadIdx.x;
    const int lane = tid & 31;
    const int w    = tid >> 5;
    const int r    = lane >> 2;
    const int l4   = lane & 3;
    const int bh   = blockIdx.y;
    const int qbase = blockIdx.x * 128;
    const float scale = 0.125f;

    const float* Qp  = g_q + (size_t)bh * TT * HD;
    const float* Kp  = g_k + (size_t)bh * TT * HD;
    const float* Vtp = g_v + (size_t)bh * HD * TT;

    // per-thread gather coordinates for K/V tile loads (4 float4 each)
    const int kt_t  = tid >> 4;          // K: row t (+64 per i? no: f = tid + i*256)
    // We'll recompute per i inside helpers to keep exact old mapping.

    // Stage Q (128x64) into Ps with intra-8 d-permute
#pragma unroll
    for (int i = 0; i < 8; i++) {
        int f = tid + i * 256;
        int t = f >> 4, dq = f & 15;
        float4 v = *(const float4*)(Qp + (size_t)(qbase + t) * HD + dq * 4);
        float* dst = Ps + t * AT_PAD + (dq >> 1) * 8 + (dq & 1);
        dst[0] = v.x; dst[2] = v.y; dst[4] = v.z; dst[6] = v.w;
    }

    // Preload tile 0 (LDG -> regs -> STS buf0)
    float4 kreg[4], vreg[4];
#pragma unroll
    for (int i = 0; i < 4; i++) {
        int f = tid + i * 256;
        int t = f >> 4, dq = f & 15;
        kreg[i] = *(const float4*)(Kp + (size_t)t * HD + dq * 4);
        int d = f >> 4, t4 = f & 15;
        vreg[i] = *(const float4*)(Vtp + (size_t)d * TT + t4 * 4);
    }
#pragma unroll
    for (int i = 0; i < 4; i++) {
        int f = tid + i * 256;
        int t = f >> 4, dq = f & 15;
        float* dst = Kb[0] + t * AT_PAD + (dq >> 1) * 8 + (dq & 1);
        dst[0] = kreg[i].x; dst[2] = kreg[i].y; dst[4] = kreg[i].z; dst[6] = kreg[i].w;
        int d = f >> 4, t4 = f & 15;
        float* dv = Vb[0] + d * AT_PAD + (t4 >> 1) * 8 + (t4 & 1);
        dv[0] = vreg[i].x; dv[2] = vreg[i].y; dv[4] = vreg[i].z; dv[6] = vreg[i].w;
    }
    __syncthreads();

    // Q fragments (registers, whole kernel)
    float aq[8][4];
    {
        const float* q0 = Ps + (w * 16 + r) * AT_PAD + l4 * 2;
        const float* q1 = q0 + 8 * AT_PAD;
#pragma unroll
        for (int k = 0; k < 8; k++) {
            float2 f = *(const float2*)(q0 + k * 8);
            float2 g = *(const float2*)(q1 + k * 8);
            aq[k][0] = f.x; aq[k][1] = g.x; aq[k][2] = f.y; aq[k][3] = g.y;
        }
    }

    float O[8][4];
#pragma unroll
    for (int nt = 0; nt < 8; nt++)
#pragma unroll
        for (int j = 0; j < 4; j++) O[nt][j] = 0.0f;
    float m0v = -1e30f, m1v = -1e30f, l0v = 0.0f, l1v = 0.0f;

    const int tq0 = qbase + w * 16 + r;
    const int tq1 = tq0 + 8;
    const int ntiles = 2 * blockIdx.x + 2;
    float* pw = Ps + (w * 16) * AT_PAD;
    const int pos0 = (l4 < 2) ? l4 * 4 : (l4 - 2) * 4 + 1;

    for (int kt = 0; kt < ntiles; kt++) {
        const int kbase = kt * 64;
        const int buf = kt & 1;
        const float* Ksm = Kb[buf];
        const float* VTs = Vb[buf];
        const bool more = (kt + 1 < ntiles);

        // Prefetch next tile into registers (latency hidden behind compute)
        if (more) {
            const int nb = kbase + 64;
#pragma unroll
            for (int i = 0; i < 4; i++) {
                int f = tid + i * 256;
                int t = f >> 4, dq = f & 15;
                kreg[i] = *(const float4*)(Kp + (size_t)(nb + t) * HD + dq * 4);
                int d = f >> 4, t4 = f & 15;
                vreg[i] = *(const float4*)(Vtp + (size_t)d * TT + nb + t4 * 4);
            }
        }

        // S = Q K^T
        float s[8][4];
#pragma unroll
        for (int nt = 0; nt < 8; nt++) {
#pragma unroll
            for (int j = 0; j < 4; j++) s[nt][j] = 0.0f;
            const float* kp = Ksm + (nt * 8 + r) * AT_PAD + l4 * 2;
#pragma unroll
            for (int k = 0; k < 8; k++) {
                float2 b = *(const float2*)(kp + k * 8);
                mma_tf32(s[nt], aq[k][0], aq[k][1], aq[k][2], aq[k][3], b.x, b.y);
            }
        }

        // scale + causal mask
        if (kbase + 63 <= qbase + w * 16) {
#pragma unroll
            for (int nt = 0; nt < 8; nt++)
#pragma unroll
                for (int j = 0; j < 4; j++) s[nt][j] *= scale;
        } else {
#pragma unroll
            for (int nt = 0; nt < 8; nt++) {
                int tk = kbase + nt * 8 + 2 * l4;
                s[nt][0] = (tk     <= tq0) ? s[nt][0] * scale : -1e30f;
                s[nt][1] = (tk + 1 <= tq0) ? s[nt][1] * scale : -1e30f;
                s[nt][2] = (tk     <= tq1) ? s[nt][2] * scale : -1e30f;
                s[nt][3] = (tk + 1 <= tq1) ? s[nt][3] * scale : -1e30f;
            }
        }

        // online softmax
        float ml0 = -1e30f, ml1 = -1e30f;
#pragma unroll
        for (int nt = 0; nt < 8; nt++) {
            ml0 = fmaxf(ml0, fmaxf(s[nt][0], s[nt][1]));
            ml1 = fmaxf(ml1, fmaxf(s[nt][2], s[nt][3]));
        }
        ml0 = fmaxf(ml0, __shfl_xor_sync(0xffffffffu, ml0, 1));
        ml0 = fmaxf(ml0, __shfl_xor_sync(0xffffffffu, ml0, 2));
        ml1 = fmaxf(ml1, __shfl_xor_sync(0xffffffffu, ml1, 1));
        ml1 = fmaxf(ml1, __shfl_xor_sync(0xffffffffu, ml1, 2));
        float mn0 = fmaxf(m0v, ml0), mn1 = fmaxf(m1v, ml1);
        float c0 = __expf(m0v - mn0), c1 = __expf(m1v - mn1);
        float ps0 = 0.0f, ps1 = 0.0f;
#pragma unroll
        for (int nt = 0; nt < 8; nt++) {
            s[nt][0] = __expf(s[nt][0] - mn0); ps0 += s[nt][0];
            s[nt][1] = __expf(s[nt][1] - mn0); ps0 += s[nt][1];
            s[nt][2] = __expf(s[nt][2] - mn1); ps1 += s[nt][2];
            s[nt][3] = __expf(s[nt][3] - mn1); ps1 += s[nt][3];
        }
        ps0 += __shfl_xor_sync(0xffffffffu, ps0, 1);
        ps0 += __shfl_xor_sync(0xffffffffu, ps0, 2);
        ps1 += __shfl_xor_sync(0xffffffffu, ps1, 1);
        ps1 += __shfl_xor_sync(0xffffffffu, ps1, 2);
        l0v = l0v * c0 + ps0; m0v = mn0;
        l1v = l1v * c1 + ps1; m1v = mn1;
#pragma unroll
        for (int nt = 0; nt < 8; nt++) {
            O[nt][0] *= c0; O[nt][1] *= c0;
            O[nt][2] *= c1; O[nt][3] *= c1;
        }

        // P -> per-warp smem (own rows only; syncwarp suffices)
#pragma unroll
        for (int nt = 0; nt < 8; nt++) {
            float* p0 = pw + r * AT_PAD + nt * 8 + pos0;
            float* p1 = pw + (r + 8) * AT_PAD + nt * 8 + pos0;
            p0[0] = to_tf32(s[nt][0]); p0[2] = to_tf32(s[nt][1]);
            p1[0] = to_tf32(s[nt][2]); p1[2] = to_tf32(s[nt][3]);
        }
        __syncwarp();

        float pa[8][4];
        {
            const float* p0 = pw + r * AT_PAD + l4 * 2;
            const float* p1 = p0 + 8 * AT_PAD;
#pragma unroll
            for (int k = 0; k < 8; k++) {
                float2 f = *(const float2*)(p0 + k * 8);
                float2 g = *(const float2*)(p1 + k * 8);
                pa[k][0] = f.x; pa[k][1] = g.x; pa[k][2] = f.y; pa[k][3] = g.y;
            }
        }

        // O += P V
#pragma unroll
        for (int nt = 0; nt < 8; nt++) {
            const float* vp = VTs + (nt * 8 + r) * AT_PAD + l4 * 2;
#pragma unroll
            for (int k = 0; k < 8; k++) {
                float2 b = *(const float2*)(vp + k * 8);
                mma_tf32(O[nt], pa[k][0], pa[k][1], pa[k][2], pa[k][3], b.x, b.y);
            }
        }

        // Store prefetched tile into the other buffer, then one barrier
        if (more) {
            float* Kd = Kb[buf ^ 1];
            float* Vd = Vb[buf ^ 1];
#pragma unroll
            for (int i = 0; i < 4; i++) {
                int f = tid + i * 256;
                int t = f >> 4, dq = f & 15;
                float* dst = Kd + t * AT_PAD + (dq >> 1) * 8 + (dq & 1);
                dst[0] = kreg[i].x; dst[2] = kreg[i].y;
                dst[4] = kreg[i].z; dst[6] = kreg[i].w;
                int d = f >> 4, t4 = f & 15;
                float* dv = Vd + d * AT_PAD + (t4 >> 1) * 8 + (t4 & 1);
                dv[0] = vreg[i].x; dv[2] = vreg[i].y;
                dv[4] = vreg[i].z; dv[6] = vreg[i].w;
            }
            __syncthreads();
        }
    }

    // Epilogue: normalize, write y permuted+tf32 for proj GEMM
    const int b = bh >> 4;
    const int h = bh & 15;
    const int hb = h * 64;
    const float inv0 = 1.0f / l0v, inv1 = 1.0f / l1v;
    float* y0 = Yg + (size_t)(b * TT + tq0) * CC;
    float* y1 = Yg + (size_t)(b * TT + tq1) * CC;
#pragma unroll
    for (int nt = 0; nt < 8; nt++) {
        int c = hb + nt * 8 + 2 * l4;
        int base = c & ~31;
        int k5 = c & 31, k51 = (c + 1) & 31;
        int p0 = (k5 & 3) * 8 + (k5 >> 2);
        int p1 = (k51 & 3) * 8 + (k51 >> 2);
        y0[base + p0] = to_tf32(O[nt][0] * inv0);
        y0[base + p1] = to_tf32(O[nt][1] * inv0);
        y1[base + p0] = to_tf32(O[nt][2] * inv1);
        y1[base + p1] = to_tf32(O[nt][3] * inv1);
    }
}

// ---------------------------------------------------------------------------
// Launch
// ---------------------------------------------------------------------------
extern "C" void kernel_launch(void* const* d_in, const int* in_sizes, int n_in,
                              void* d_out, int out_size)
{
    const float* x     = (const float*)d_in[0];
    const float* Wqkv  = (const float*)d_in[1];
    const float* bqkv  = (const float*)d_in[2];
    const float* Wproj = (const float*)d_in[3];
    const float* bproj = (const float*)d_in[4];
    float* out = (float*)d_out;
    (void)in_sizes; (void)n_in; (void)out_size;

    float *yp, *xp, *wtq, *wtp;
    cudaGetSymbolAddress((void**)&yp,  g_y);
    cudaGetSymbolAddress((void**)&xp,  g_xp);
    cudaGetSymbolAddress((void**)&wtq, g_wtq);
    cudaGetSymbolAddress((void**)&wtp, g_wtp);

    cudaFuncSetAttribute(mma_gemm<0>, cudaFuncAttributeMaxDynamicSharedMemorySize, GEMM_SMEM);
    cudaFuncSetAttribute(mma_gemm<1>, cudaFuncAttributeMaxDynamicSharedMemorySize, GEMM_SMEM);
    cudaFuncSetAttribute(attn_mma,    cudaFuncAttributeMaxDynamicSharedMemorySize, AT_SMEM);

    {
        int total4 = MROWS * CC / 4;
        prep_A<<<(total4 + 255) / 256, 256>>>(x, xp, total4, CC);
        transpose_perm<<<dim3(N_QKV / 32, CC / 32), dim3(32, 8)>>>(Wqkv, wtq, CC, N_QKV);
        transpose_perm<<<dim3(CC / 32, CC / 32), dim3(32, 8)>>>(Wproj, wtp, CC, CC);
    }

    mma_gemm<0><<<dim3(N_QKV / 128, MROWS / 128), 256, GEMM_SMEM>>>(xp, wtq, bqkv, nullptr, N_QKV);
    attn_mma<<<dim3(TT / 128, BB * HH), 256, AT_SMEM>>>(yp);
    mma_gemm<1><<<dim3(CC / 128, MROWS / 128), 256, GEMM_SMEM>>>(yp, wtp, bproj, out, CC);
}

// round 7
// speedup vs baseline: 1.0867x; 1.0867x over previous
#include <cuda_runtime.h>
#include <math.h>
#include <stdint.h>

#define BB   2
#define TT   2048
#define CC   1024
#define HH   16
#define HD   64
#define MROWS (BB*TT)        // 4096
#define N_QKV (3*CC)         // 3072

// ---------------------------------------------------------------------------
// Scratch (device globals)
// ---------------------------------------------------------------------------
__device__ __align__(1024) float g_q[BB*HH*TT*HD];   // [B,H,T,HD]  tf32
__device__ __align__(1024) float g_k[BB*HH*TT*HD];   // [B,H,T,HD]  tf32
__device__ __align__(1024) float g_v[BB*HH*TT*HD];   // [B,H,HD,T]  tf32 (TRANSPOSED)
__device__ __align__(1024) float g_y[MROWS*CC];      // attn out, PERMUTED tf32
__device__ __align__(1024) float g_xp[MROWS*CC];     // x, PERMUTED tf32
__device__ __align__(1024) float g_wtq[N_QKV*CC];    // Wqkv^T, PERMUTED tf32
__device__ __align__(1024) float g_wtp[CC*CC];       // Wproj^T, PERMUTED tf32

// ---------------------------------------------------------------------------
// Helpers
// ---------------------------------------------------------------------------
__device__ __forceinline__ float to_tf32(float x) {
    float r;
    asm("cvt.rna.tf32.f32 %0, %1;" : "=f"(r) : "f"(x));
    return r;
}

__device__ __forceinline__ uint32_t s2u(const void* p) {
    uint32_t a;
    asm("{ .reg .u64 t; cvta.to.shared.u64 t, %1; cvt.u32.u64 %0, t; }"
        : "=r"(a) : "l"(p));
    return a;
}

__device__ __forceinline__ void cp_async16(uint32_t dst, const float* src) {
    asm volatile("cp.async.cg.shared.global [%0], [%1], 16;"
                 :: "r"(dst), "l"(src) : "memory");
}

__device__ __forceinline__ float f4e(const float4& v, int i) {
    return i == 0 ? v.x : (i == 1 ? v.y : (i == 2 ? v.z : v.w));
}

__device__ __forceinline__ void mma_tf32(float d[4], float a0, float a1,
                                         float a2, float a3, float b0, float b1)
{
    asm volatile(
        "mma.sync.aligned.m16n8k8.row.col.f32.tf32.tf32.f32 "
        "{%0,%1,%2,%3}, {%4,%5,%6,%7}, {%8,%9}, {%0,%1,%2,%3};"
        : "+f"(d[0]), "+f"(d[1]), "+f"(d[2]), "+f"(d[3])
        : "r"(__float_as_uint(a0)), "r"(__float_as_uint(a1)),
          "r"(__float_as_uint(a2)), "r"(__float_as_uint(a3)),
          "r"(__float_as_uint(b0)), "r"(__float_as_uint(b1)));
}

// ---------------------------------------------------------------------------
// Prep kernels
// ---------------------------------------------------------------------------
__global__ void prep_A(const float* __restrict__ in, float* __restrict__ out,
                       int total4, int K)
{
    int idx = blockIdx.x * 256 + threadIdx.x;
    if (idx >= total4) return;
    int row = idx / (K / 4);
    int k   = (idx % (K / 4)) * 4;
    float4 v = *(const float4*)(in + (size_t)row * K + k);
    int kb = k & ~31;
    int q  = (k & 31) >> 2;
    float* o = out + (size_t)row * K + kb;
    o[q]      = to_tf32(v.x);
    o[8 + q]  = to_tf32(v.y);
    o[16 + q] = to_tf32(v.z);
    o[24 + q] = to_tf32(v.w);
}

__global__ void transpose_perm(const float* __restrict__ in,
                               float* __restrict__ out, int R, int C)
{
    __shared__ float t[32][33];
    int c0 = blockIdx.x * 32, r0 = blockIdx.y * 32;
    int x = threadIdx.x, y = threadIdx.y;
#pragma unroll
    for (int i = 0; i < 32; i += 8)
        t[y + i][x] = in[(size_t)(r0 + y + i) * C + c0 + x];
    __syncthreads();
    int xp = (x & 3) * 8 + (x >> 2);
#pragma unroll
    for (int i = 0; i < 32; i += 8)
        out[(size_t)(c0 + y + i) * R + r0 + xp] = to_tf32(t[x][y + i]);
}

// ---------------------------------------------------------------------------
// TF32 mma.sync GEMM. CTA 128x128, 128 threads, 4 warps (2x2), warp tile
// 64x64. Single-sync 3-stage cp.async pipeline, 2 CTAs/SM.
// Fragments loaded per k=16 half to bound register pressure.
// ---------------------------------------------------------------------------
#define GSTAGES 3
#define KB      32
#define APAD    36
#define TILE_F  (128*APAD)
#define GEMM_SMEM (GSTAGES*2*TILE_F*4)

__device__ __forceinline__ void g_load_stage(uint32_t sbase, int s,
                                             const float* Ag, const float* Bg,
                                             int k0, int tid)
{
    uint32_t base = sbase + (uint32_t)s * 2 * TILE_F * 4;
#pragma unroll
    for (int i = 0; i < 8; i++) {
        int f = tid + i * 128;          // 0..1023
        int row = f >> 3, c = f & 7;
        cp_async16(base + row * (APAD * 4) + c * 16,
                   Ag + (size_t)row * CC + k0 + c * 4);
        cp_async16(base + TILE_F * 4 + row * (APAD * 4) + c * 16,
                   Bg + (size_t)row * CC + k0 + c * 4);
    }
    asm volatile("cp.async.commit_group;" ::: "memory");
}

template <int MODE>
__global__ __launch_bounds__(128, 2)
void mma_gemm(const float* __restrict__ A, const float* __restrict__ Bt,
              const float* __restrict__ bias, float* __restrict__ Cout, int Nn)
{
    extern __shared__ __align__(16) float sm[];
    const uint32_t sbase = s2u(sm);
    const int tid  = threadIdx.x;
    const int lane = tid & 31;
    const int wid  = tid >> 5;          // 0..3
    const int wm   = wid & 1;           // 2 along M
    const int wn   = wid >> 1;          // 2 along N
    const int r    = lane >> 2;
    const int l4   = lane & 3;
    const int m0 = blockIdx.y * 128;
    const int n0 = blockIdx.x * 128;

    const float* Ag = A + (size_t)m0 * CC;
    const float* Bg = Bt + (size_t)n0 * CC;

    float acc[4][8][4];
#pragma unroll
    for (int mt = 0; mt < 4; mt++)
#pragma unroll
        for (int nt = 0; nt < 8; nt++)
#pragma unroll
            for (int j = 0; j < 4; j++) acc[mt][nt][j] = 0.0f;

    const int NIT = CC / KB;   // 32

#pragma unroll
    for (int s = 0; s < GSTAGES - 1; s++)
        g_load_stage(sbase, s, Ag, Bg, s * KB, tid);

    for (int it = 0; it < NIT; it++) {
        if (it < NIT - 1)
            asm volatile("cp.async.wait_group %0;" :: "n"(GSTAGES - 2) : "memory");
        else
            asm volatile("cp.async.wait_group 0;" ::: "memory");
        __syncthreads();

        if (it + GSTAGES - 1 < NIT)
            g_load_stage(sbase, (it + GSTAGES - 1) % GSTAGES, Ag, Bg,
                         (it + GSTAGES - 1) * KB, tid);

        const float* As = sm + (size_t)(it % GSTAGES) * 2 * TILE_F;
        const float* Bs = As + TILE_F;

#pragma unroll
        for (int hi = 0; hi < 2; hi++) {
            float4 afh[4][2];
#pragma unroll
            for (int mt = 0; mt < 4; mt++) {
                const float* ap = As + (wm * 64 + mt * 16 + r) * APAD
                                     + l4 * 8 + hi * 4;
                afh[mt][0] = *(const float4*)ap;
                afh[mt][1] = *(const float4*)(ap + 8 * APAD);
            }
            float4 bfh[8];
#pragma unroll
            for (int nt = 0; nt < 8; nt++) {
                const float* bp = Bs + (wn * 64 + nt * 8 + r) * APAD
                                     + l4 * 8 + hi * 4;
                bfh[nt] = *(const float4*)bp;
            }
#pragma unroll
            for (int g2 = 0; g2 < 2; g2++) {
                const int e0 = g2 * 2, e1 = e0 + 1;
#pragma unroll
                for (int mt = 0; mt < 4; mt++) {
                    float a0 = f4e(afh[mt][0], e0);
                    float a1 = f4e(afh[mt][1], e0);
                    float a2 = f4e(afh[mt][0], e1);
                    float a3 = f4e(afh[mt][1], e1);
#pragma unroll
                    for (int nt = 0; nt < 8; nt++) {
                        float b0 = f4e(bfh[nt], e0);
                        float b1 = f4e(bfh[nt], e1);
                        mma_tf32(acc[mt][nt], a0, a1, a2, a3, b0, b1);
                    }
                }
            }
        }
    }

#pragma unroll
    for (int mt = 0; mt < 4; mt++) {
#pragma unroll
        for (int nt = 0; nt < 8; nt++) {
            const int row = m0 + wm * 64 + mt * 16 + r;
            const int c   = n0 + wn * 64 + nt * 8 + 2 * l4;
            const float b0v = __ldg(bias + c);
            const float b1v = __ldg(bias + c + 1);
            float v00 = acc[mt][nt][0] + b0v, v01 = acc[mt][nt][1] + b1v;
            float v10 = acc[mt][nt][2] + b0v, v11 = acc[mt][nt][3] + b1v;
            if (MODE == 0) {
                const int sec = c >> 10;
                const int cs = c & 1023, h = cs >> 6, d0 = cs & 63;
                const int b  = row >> 11;
                const int t0 = row & 2047;
                const int t1 = (row + 8) & 2047;
                if (sec == 2) {
                    float* vb = g_v + ((size_t)(b * HH + h) * HD) * TT;
                    vb[(size_t)d0 * TT + t0]       = to_tf32(v00);
                    vb[(size_t)(d0 + 1) * TT + t0] = to_tf32(v01);
                    vb[(size_t)d0 * TT + t1]       = to_tf32(v10);
                    vb[(size_t)(d0 + 1) * TT + t1] = to_tf32(v11);
                } else {
                    float* basep = (sec == 0) ? g_q : g_k;
                    float* p0 = basep + (((size_t)(b * HH + h) * TT + t0) * HD + d0);
                    float* p1 = basep + (((size_t)(b * HH + h) * TT + t1) * HD + d0);
                    *(float2*)p0 = make_float2(to_tf32(v00), to_tf32(v01));
                    *(float2*)p1 = make_float2(to_tf32(v10), to_tf32(v11));
                }
            } else {
                *(float2*)(Cout + (size_t)row * Nn + c)       = make_float2(v00, v01);
                *(float2*)(Cout + (size_t)(row + 8) * Nn + c) = make_float2(v10, v11);
            }
        }
    }
}

// ---------------------------------------------------------------------------
// Flash attention on tf32 mma.sync (round-5 version, proven fastest).
// ---------------------------------------------------------------------------
#define AT_PAD  72
#define AT_SMEM ((64*AT_PAD*2 + 128*AT_PAD)*4)

__global__ __launch_bounds__(256, 1)
void attn_mma(float* __restrict__ Yg)
{
    extern __shared__ __align__(16) float smf[];
    float* Ksm = smf;                       // [64][72]
    float* VTs = smf + 64 * AT_PAD;         // [64][72]
    float* Ps  = smf + 128 * AT_PAD;        // [128][72]

    const int tid  = threadIdx.x;
    const int lane = tid & 31;
    const int w    = tid >> 5;
    const int r    = lane >> 2;
    const int l4   = lane & 3;
    const int bh   = blockIdx.y;
    const int qbase = blockIdx.x * 128;
    const float scale = 0.125f;

    const float* Qp  = g_q + (size_t)bh * TT * HD;
    const float* Kp  = g_k + (size_t)bh * TT * HD;
    const float* Vtp = g_v + (size_t)bh * HD * TT;

#pragma unroll
    for (int i = 0; i < 8; i++) {
        int f = tid + i * 256;
        int t = f >> 4, dq = f & 15;
        float4 v = *(const float4*)(Qp + (size_t)(qbase + t) * HD + dq * 4);
        float* dst = Ps + t * AT_PAD + (dq >> 1) * 8 + (dq & 1);
        dst[0] = v.x; dst[2] = v.y; dst[4] = v.z; dst[6] = v.w;
    }
    __syncthreads();

    float aq[8][4];
    {
        const float* q0 = Ps + (w * 16 + r) * AT_PAD + l4 * 2;
        const float* q1 = q0 + 8 * AT_PAD;
#pragma unroll
        for (int k = 0; k < 8; k++) {
            float2 f = *(const float2*)(q0 + k * 8);
            float2 g = *(const float2*)(q1 + k * 8);
            aq[k][0] = f.x; aq[k][1] = g.x; aq[k][2] = f.y; aq[k][3] = g.y;
        }
    }

    float O[8][4];
#pragma unroll
    for (int nt = 0; nt < 8; nt++)
#pragma unroll
        for (int j = 0; j < 4; j++) O[nt][j] = 0.0f;
    float m0v = -1e30f, m1v = -1e30f, l0v = 0.0f, l1v = 0.0f;

    const int tq0 = qbase + w * 16 + r;
    const int tq1 = tq0 + 8;
    const int ntiles = 2 * blockIdx.x + 2;
    float* pw = Ps + (w * 16) * AT_PAD;
    const int pos0 = (l4 < 2) ? l4 * 4 : (l4 - 2) * 4 + 1;

    for (int kt = 0; kt < ntiles; kt++) {
        const int kbase = kt * 64;
        __syncthreads();
#pragma unroll
        for (int i = 0; i < 4; i++) {
            int f = tid + i * 256;
            int t = f >> 4, dq = f & 15;
            float4 v = *(const float4*)(Kp + (size_t)(kbase + t) * HD + dq * 4);
            float* dst = Ksm + t * AT_PAD + (dq >> 1) * 8 + (dq & 1);
            dst[0] = v.x; dst[2] = v.y; dst[4] = v.z; dst[6] = v.w;
        }
#pragma unroll
        for (int i = 0; i < 4; i++) {
            int f = tid + i * 256;
            int d = f >> 4, t4 = f & 15;
            float4 v = *(const float4*)(Vtp + (size_t)d * TT + kbase + t4 * 4);
            float* dst = VTs + d * AT_PAD + (t4 >> 1) * 8 + (t4 & 1);
            dst[0] = v.x; dst[2] = v.y; dst[4] = v.z; dst[6] = v.w;
        }
        __syncthreads();

        float s[8][4];
#pragma unroll
        for (int nt = 0; nt < 8; nt++) {
#pragma unroll
            for (int j = 0; j < 4; j++) s[nt][j] = 0.0f;
            const float* kp = Ksm + (nt * 8 + r) * AT_PAD + l4 * 2;
#pragma unroll
            for (int k = 0; k < 8; k++) {
                float2 b = *(const float2*)(kp + k * 8);
                mma_tf32(s[nt], aq[k][0], aq[k][1], aq[k][2], aq[k][3], b.x, b.y);
            }
        }

        if (kbase + 63 <= qbase + w * 16) {
#pragma unroll
            for (int nt = 0; nt < 8; nt++)
#pragma unroll
                for (int j = 0; j < 4; j++) s[nt][j] *= scale;
        } else {
#pragma unroll
            for (int nt = 0; nt < 8; nt++) {
                int tk = kbase + nt * 8 + 2 * l4;
                s[nt][0] = (tk     <= tq0) ? s[nt][0] * scale : -1e30f;
                s[nt][1] = (tk + 1 <= tq0) ? s[nt][1] * scale : -1e30f;
                s[nt][2] = (tk     <= tq1) ? s[nt][2] * scale : -1e30f;
                s[nt][3] = (tk + 1 <= tq1) ? s[nt][3] * scale : -1e30f;
            }
        }

        float ml0 = -1e30f, ml1 = -1e30f;
#pragma unroll
        for (int nt = 0; nt < 8; nt++) {
            ml0 = fmaxf(ml0, fmaxf(s[nt][0], s[nt][1]));
            ml1 = fmaxf(ml1, fmaxf(s[nt][2], s[nt][3]));
        }
        ml0 = fmaxf(ml0, __shfl_xor_sync(0xffffffffu, ml0, 1));
        ml0 = fmaxf(ml0, __shfl_xor_sync(0xffffffffu, ml0, 2));
        ml1 = fmaxf(ml1, __shfl_xor_sync(0xffffffffu, ml1, 1));
        ml1 = fmaxf(ml1, __shfl_xor_sync(0xffffffffu, ml1, 2));
        float mn0 = fmaxf(m0v, ml0), mn1 = fmaxf(m1v, ml1);
        float c0 = __expf(m0v - mn0), c1 = __expf(m1v - mn1);
        float ps0 = 0.0f, ps1 = 0.0f;
#pragma unroll
        for (int nt = 0; nt < 8; nt++) {
            s[nt][0] = __expf(s[nt][0] - mn0); ps0 += s[nt][0];
            s[nt][1] = __expf(s[nt][1] - mn0); ps0 += s[nt][1];
            s[nt][2] = __expf(s[nt][2] - mn1); ps1 += s[nt][2];
            s[nt][3] = __expf(s[nt][3] - mn1); ps1 += s[nt][3];
        }
        ps0 += __shfl_xor_sync(0xffffffffu, ps0, 1);
        ps0 += __shfl_xor_sync(0xffffffffu, ps0, 2);
        ps1 += __shfl_xor_sync(0xffffffffu, ps1, 1);
        ps1 += __shfl_xor_sync(0xffffffffu, ps1, 2);
        l0v = l0v * c0 + ps0; m0v = mn0;
        l1v = l1v * c1 + ps1; m1v = mn1;
#pragma unroll
        for (int nt = 0; nt < 8; nt++) {
            O[nt][0] *= c0; O[nt][1] *= c0;
            O[nt][2] *= c1; O[nt][3] *= c1;
        }

#pragma unroll
        for (int nt = 0; nt < 8; nt++) {
            float* p0 = pw + r * AT_PAD + nt * 8 + pos0;
            float* p1 = pw + (r + 8) * AT_PAD + nt * 8 + pos0;
            p0[0] = to_tf32(s[nt][0]); p0[2] = to_tf32(s[nt][1]);
            p1[0] = to_tf32(s[nt][2]); p1[2] = to_tf32(s[nt][3]);
        }
        __syncwarp();

        float pa[8][4];
        {
            const float* p0 = pw + r * AT_PAD + l4 * 2;
            const float* p1 = p0 + 8 * AT_PAD;
#pragma unroll
            for (int k = 0; k < 8; k++) {
                float2 f = *(const float2*)(p0 + k * 8);
                float2 g = *(const float2*)(p1 + k * 8);
                pa[k][0] = f.x; pa[k][1] = g.x; pa[k][2] = f.y; pa[k][3] = g.y;
            }
        }

#pragma unroll
        for (int nt = 0; nt < 8; nt++) {
            const float* vp = VTs + (nt * 8 + r) * AT_PAD + l4 * 2;
#pragma unroll
            for (int k = 0; k < 8; k++) {
                float2 b = *(const float2*)(vp + k * 8);
                mma_tf32(O[nt], pa[k][0], pa[k][1], pa[k][2], pa[k][3], b.x, b.y);
            }
        }
    }

    const int b = bh >> 4;
    const int h = bh & 15;
    const int hb = h * 64;
    const float inv0 = 1.0f / l0v, inv1 = 1.0f / l1v;
    float* y0 = Yg + (size_t)(b * TT + tq0) * CC;
    float* y1 = Yg + (size_t)(b * TT + tq1) * CC;
#pragma unroll
    for (int nt = 0; nt < 8; nt++) {
        int c = hb + nt * 8 + 2 * l4;
        int base = c & ~31;
        int k5 = c & 31, k51 = (c + 1) & 31;
        int p0 = (k5 & 3) * 8 + (k5 >> 2);
        int p1 = (k51 & 3) * 8 + (k51 >> 2);
        y0[base + p0] = to_tf32(O[nt][0] * inv0);
        y0[base + p1] = to_tf32(O[nt][1] * inv0);
        y1[base + p0] = to_tf32(O[nt][2] * inv1);
        y1[base + p1] = to_tf32(O[nt][3] * inv1);
    }
}

// ---------------------------------------------------------------------------
// Launch
// ---------------------------------------------------------------------------
extern "C" void kernel_launch(void* const* d_in, const int* in_sizes, int n_in,
                              void* d_out, int out_size)
{
    const float* x     = (const float*)d_in[0];
    const float* Wqkv  = (const float*)d_in[1];
    const float* bqkv  = (const float*)d_in[2];
    const float* Wproj = (const float*)d_in[3];
    const float* bproj = (const float*)d_in[4];
    float* out = (float*)d_out;
    (void)in_sizes; (void)n_in; (void)out_size;

    float *yp, *xp, *wtq, *wtp;
    cudaGetSymbolAddress((void**)&yp,  g_y);
    cudaGetSymbolAddress((void**)&xp,  g_xp);
    cudaGetSymbolAddress((void**)&wtq, g_wtq);
    cudaGetSymbolAddress((void**)&wtp, g_wtp);

    cudaFuncSetAttribute(mma_gemm<0>, cudaFuncAttributeMaxDynamicSharedMemorySize, GEMM_SMEM);
    cudaFuncSetAttribute(mma_gemm<1>, cudaFuncAttributeMaxDynamicSharedMemorySize, GEMM_SMEM);
    cudaFuncSetAttribute(attn_mma,    cudaFuncAttributeMaxDynamicSharedMemorySize, AT_SMEM);

    {
        int total4 = MROWS * CC / 4;
        prep_A<<<(total4 + 255) / 256, 256>>>(x, xp, total4, CC);
        transpose_perm<<<dim3(N_QKV / 32, CC / 32), dim3(32, 8)>>>(Wqkv, wtq, CC, N_QKV);
        transpose_perm<<<dim3(CC / 32, CC / 32), dim3(32, 8)>>>(Wproj, wtp, CC, CC);
    }

    mma_gemm<0><<<dim3(N_QKV / 128, MROWS / 128), 128, GEMM_SMEM>>>(xp, wtq, bqkv, nullptr, N_QKV);
    attn_mma<<<dim3(TT / 128, BB * HH), 256, AT_SMEM>>>(yp);
    mma_gemm<1><<<dim3(CC / 128, MROWS / 128), 128, GEMM_SMEM>>>(yp, wtp, bproj, out, CC);
}

// round 8
// speedup vs baseline: 1.2215x; 1.1241x over previous
#include <cuda_runtime.h>
#include <math.h>
#include <stdint.h>

#define BB   2
#define TT   2048
#define CC   1024
#define HH   16
#define HD   64
#define MROWS (BB*TT)        // 4096
#define N_QKV (3*CC)         // 3072

// ---------------------------------------------------------------------------
// Scratch (device globals)
// ---------------------------------------------------------------------------
__device__ __align__(1024) float g_q[BB*HH*TT*HD];   // [B,H,T,HD]  tf32
__device__ __align__(1024) float g_k[BB*HH*TT*HD];   // [B,H,T,HD]  tf32
__device__ __align__(1024) float g_v[BB*HH*TT*HD];   // [B,H,HD,T]  tf32 (TRANSPOSED)
__device__ __align__(1024) float g_y[MROWS*CC];      // attn out, PERMUTED tf32
__device__ __align__(1024) float g_xp[MROWS*CC];     // x, PERMUTED tf32
__device__ __align__(1024) float g_wtq[N_QKV*CC];    // Wqkv^T, PERMUTED tf32
__device__ __align__(1024) float g_wtp[CC*CC];       // Wproj^T, PERMUTED tf32

// ---------------------------------------------------------------------------
// Helpers
// ---------------------------------------------------------------------------
__device__ __forceinline__ float to_tf32(float x) {
    float r;
    asm("cvt.rna.tf32.f32 %0, %1;" : "=f"(r) : "f"(x));
    return r;
}

__device__ __forceinline__ uint32_t s2u(const void* p) {
    uint32_t a;
    asm("{ .reg .u64 t; cvta.to.shared.u64 t, %1; cvt.u32.u64 %0, t; }"
        : "=r"(a) : "l"(p));
    return a;
}

__device__ __forceinline__ void cp_async16(uint32_t dst, const float* src) {
    asm volatile("cp.async.cg.shared.global [%0], [%1], 16;"
                 :: "r"(dst), "l"(src) : "memory");
}

__device__ __forceinline__ float f4e(const float4& v, int i) {
    return i == 0 ? v.x : (i == 1 ? v.y : (i == 2 ? v.z : v.w));
}

__device__ __forceinline__ void mma_tf32(float d[4], float a0, float a1,
                                         float a2, float a3, float b0, float b1)
{
    asm volatile(
        "mma.sync.aligned.m16n8k8.row.col.f32.tf32.tf32.f32 "
        "{%0,%1,%2,%3}, {%4,%5,%6,%7}, {%8,%9}, {%0,%1,%2,%3};"
        : "+f"(d[0]), "+f"(d[1]), "+f"(d[2]), "+f"(d[3])
        : "r"(__float_as_uint(a0)), "r"(__float_as_uint(a1)),
          "r"(__float_as_uint(a2)), "r"(__float_as_uint(a3)),
          "r"(__float_as_uint(b0)), "r"(__float_as_uint(b1)));
}

// ---------------------------------------------------------------------------
// Prep kernels
// ---------------------------------------------------------------------------
__global__ void prep_A(const float* __restrict__ in, float* __restrict__ out,
                       int total4, int K)
{
    int idx = blockIdx.x * 256 + threadIdx.x;
    if (idx >= total4) return;
    int row = idx / (K / 4);
    int k   = (idx % (K / 4)) * 4;
    float4 v = *(const float4*)(in + (size_t)row * K + k);
    int kb = k & ~31;
    int q  = (k & 31) >> 2;
    float* o = out + (size_t)row * K + kb;
    o[q]      = to_tf32(v.x);
    o[8 + q]  = to_tf32(v.y);
    o[16 + q] = to_tf32(v.z);
    o[24 + q] = to_tf32(v.w);
}

__global__ void transpose_perm(const float* __restrict__ in,
                               float* __restrict__ out, int R, int C)
{
    __shared__ float t[32][33];
    int c0 = blockIdx.x * 32, r0 = blockIdx.y * 32;
    int x = threadIdx.x, y = threadIdx.y;
#pragma unroll
    for (int i = 0; i < 32; i += 8)
        t[y + i][x] = in[(size_t)(r0 + y + i) * C + c0 + x];
    __syncthreads();
    int xp = (x & 3) * 8 + (x >> 2);
#pragma unroll
    for (int i = 0; i < 32; i += 8)
        out[(size_t)(c0 + y + i) * R + r0 + xp] = to_tf32(t[x][y + i]);
}

// ---------------------------------------------------------------------------
// TF32 mma.sync GEMM (round-7, passing — unchanged).
// ---------------------------------------------------------------------------
#define GSTAGES 3
#define KB      32
#define APAD    36
#define TILE_F  (128*APAD)
#define GEMM_SMEM (GSTAGES*2*TILE_F*4)

__device__ __forceinline__ void g_load_stage(uint32_t sbase, int s,
                                             const float* Ag, const float* Bg,
                                             int k0, int tid)
{
    uint32_t base = sbase + (uint32_t)s * 2 * TILE_F * 4;
#pragma unroll
    for (int i = 0; i < 8; i++) {
        int f = tid + i * 128;
        int row = f >> 3, c = f & 7;
        cp_async16(base + row * (APAD * 4) + c * 16,
                   Ag + (size_t)row * CC + k0 + c * 4);
        cp_async16(base + TILE_F * 4 + row * (APAD * 4) + c * 16,
                   Bg + (size_t)row * CC + k0 + c * 4);
    }
    asm volatile("cp.async.commit_group;" ::: "memory");
}

template <int MODE>
__global__ __launch_bounds__(128, 2)
void mma_gemm(const float* __restrict__ A, const float* __restrict__ Bt,
              const float* __restrict__ bias, float* __restrict__ Cout, int Nn)
{
    extern __shared__ __align__(16) float sm[];
    const uint32_t sbase = s2u(sm);
    const int tid  = threadIdx.x;
    const int lane = tid & 31;
    const int wid  = tid >> 5;
    const int wm   = wid & 1;
    const int wn   = wid >> 1;
    const int r    = lane >> 2;
    const int l4   = lane & 3;
    const int m0 = blockIdx.y * 128;
    const int n0 = blockIdx.x * 128;

    const float* Ag = A + (size_t)m0 * CC;
    const float* Bg = Bt + (size_t)n0 * CC;

    float acc[4][8][4];
#pragma unroll
    for (int mt = 0; mt < 4; mt++)
#pragma unroll
        for (int nt = 0; nt < 8; nt++)
#pragma unroll
            for (int j = 0; j < 4; j++) acc[mt][nt][j] = 0.0f;

    const int NIT = CC / KB;

#pragma unroll
    for (int s = 0; s < GSTAGES - 1; s++)
        g_load_stage(sbase, s, Ag, Bg, s * KB, tid);

    for (int it = 0; it < NIT; it++) {
        if (it < NIT - 1)
            asm volatile("cp.async.wait_group %0;" :: "n"(GSTAGES - 2) : "memory");
        else
            asm volatile("cp.async.wait_group 0;" ::: "memory");
        __syncthreads();

        if (it + GSTAGES - 1 < NIT)
            g_load_stage(sbase, (it + GSTAGES - 1) % GSTAGES, Ag, Bg,
                         (it + GSTAGES - 1) * KB, tid);

        const float* As = sm + (size_t)(it % GSTAGES) * 2 * TILE_F;
        const float* Bs = As + TILE_F;

#pragma unroll
        for (int hi = 0; hi < 2; hi++) {
            float4 afh[4][2];
#pragma unroll
            for (int mt = 0; mt < 4; mt++) {
                const float* ap = As + (wm * 64 + mt * 16 + r) * APAD
                                     + l4 * 8 + hi * 4;
                afh[mt][0] = *(const float4*)ap;
                afh[mt][1] = *(const float4*)(ap + 8 * APAD);
            }
            float4 bfh[8];
#pragma unroll
            for (int nt = 0; nt < 8; nt++) {
                const float* bp = Bs + (wn * 64 + nt * 8 + r) * APAD
                                     + l4 * 8 + hi * 4;
                bfh[nt] = *(const float4*)bp;
            }
#pragma unroll
            for (int g2 = 0; g2 < 2; g2++) {
                const int e0 = g2 * 2, e1 = e0 + 1;
#pragma unroll
                for (int mt = 0; mt < 4; mt++) {
                    float a0 = f4e(afh[mt][0], e0);
                    float a1 = f4e(afh[mt][1], e0);
                    float a2 = f4e(afh[mt][0], e1);
                    float a3 = f4e(afh[mt][1], e1);
#pragma unroll
                    for (int nt = 0; nt < 8; nt++) {
                        float b0 = f4e(bfh[nt], e0);
                        float b1 = f4e(bfh[nt], e1);
                        mma_tf32(acc[mt][nt], a0, a1, a2, a3, b0, b1);
                    }
                }
            }
        }
    }

#pragma unroll
    for (int mt = 0; mt < 4; mt++) {
#pragma unroll
        for (int nt = 0; nt < 8; nt++) {
            const int row = m0 + wm * 64 + mt * 16 + r;
            const int c   = n0 + wn * 64 + nt * 8 + 2 * l4;
            const float b0v = __ldg(bias + c);
            const float b1v = __ldg(bias + c + 1);
            float v00 = acc[mt][nt][0] + b0v, v01 = acc[mt][nt][1] + b1v;
            float v10 = acc[mt][nt][2] + b0v, v11 = acc[mt][nt][3] + b1v;
            if (MODE == 0) {
                const int sec = c >> 10;
                const int cs = c & 1023, h = cs >> 6, d0 = cs & 63;
                const int b  = row >> 11;
                const int t0 = row & 2047;
                const int t1 = (row + 8) & 2047;
                if (sec == 2) {
                    float* vb = g_v + ((size_t)(b * HH + h) * HD) * TT;
                    vb[(size_t)d0 * TT + t0]       = to_tf32(v00);
                    vb[(size_t)(d0 + 1) * TT + t0] = to_tf32(v01);
                    vb[(size_t)d0 * TT + t1]       = to_tf32(v10);
                    vb[(size_t)(d0 + 1) * TT + t1] = to_tf32(v11);
                } else {
                    float* basep = (sec == 0) ? g_q : g_k;
                    float* p0 = basep + (((size_t)(b * HH + h) * TT + t0) * HD + d0);
                    float* p1 = basep + (((size_t)(b * HH + h) * TT + t1) * HD + d0);
                    *(float2*)p0 = make_float2(to_tf32(v00), to_tf32(v01));
                    *(float2*)p1 = make_float2(to_tf32(v10), to_tf32(v11));
                }
            } else {
                *(float2*)(Cout + (size_t)row * Nn + c)       = make_float2(v00, v01);
                *(float2*)(Cout + (size_t)(row + 8) * Nn + c) = make_float2(v10, v11);
            }
        }
    }
}

// ---------------------------------------------------------------------------
// Flash attention (tf32 mma). Natural smem layout + cp.async double-buffered
// K/V (no register prefetch) + heavy-tile-first CTA remap.
// smem: Kb[2][64][72], Vb[2][64][72], Ps[128][72] (Q staging then P).
// ---------------------------------------------------------------------------
#define AT_PAD  72
#define AT_SMEM ((4*64*AT_PAD + 128*AT_PAD)*4)

__device__ __forceinline__ void at_load_kv(uint32_t kdst, uint32_t vdst,
                                           const float* Kp, const float* Vtp,
                                           int kbase, int tid)
{
#pragma unroll
    for (int i = 0; i < 4; i++) {
        int f = tid + i * 256;
        int t = f >> 4, dq = f & 15;
        cp_async16(kdst + (t * AT_PAD + dq * 4) * 4,
                   Kp + (size_t)(kbase + t) * HD + dq * 4);
        // V^T: row d, contiguous along t
        cp_async16(vdst + (t * AT_PAD + dq * 4) * 4,
                   Vtp + (size_t)t * TT + kbase + dq * 4);
    }
    asm volatile("cp.async.commit_group;" ::: "memory");
}

__global__ __launch_bounds__(256, 1)
void attn_mma(float* __restrict__ Yg)
{
    extern __shared__ __align__(16) float smf[];
    float* Kb0 = smf;
    float* Kb1 = smf + 64 * AT_PAD;
    float* Vb0 = smf + 2 * 64 * AT_PAD;
    float* Vb1 = smf + 3 * 64 * AT_PAD;
    float* Ps  = smf + 4 * 64 * AT_PAD;     // [128][72]
    const uint32_t sb = s2u(smf);

    const int tid  = threadIdx.x;
    const int lane = tid & 31;
    const int w    = tid >> 5;
    const int r    = lane >> 2;
    const int l4   = lane & 3;
    const int bh   = blockIdx.y;
    const int qt   = gridDim.x - 1 - blockIdx.x;    // heavy tiles first
    const int qbase = qt * 128;
    const float scale = 0.125f;

    const float* Qp  = g_q + (size_t)bh * TT * HD;
    const float* Kp  = g_k + (size_t)bh * TT * HD;
    const float* Vtp = g_v + (size_t)bh * HD * TT;

    const uint32_t koff = (uint32_t)(64 * AT_PAD * 4);

    // Stage Q (natural layout) via cp.async into Ps
#pragma unroll
    for (int i = 0; i < 8; i++) {
        int f = tid + i * 256;
        int t = f >> 4, dq = f & 15;
        cp_async16(sb + (uint32_t)(4 * 64 * AT_PAD + t * AT_PAD + dq * 4) * 4,
                   Qp + (size_t)(qbase + t) * HD + dq * 4);
    }
    asm volatile("cp.async.commit_group;" ::: "memory");
    // Tile 0 K/V into buffer 0
    at_load_kv(sb, sb + 2 * koff, Kp, Vtp, 0, tid);
    asm volatile("cp.async.wait_group 0;" ::: "memory");
    __syncthreads();

    // Q fragments (natural: float2 at row*PAD + k*8 + 2*l4)
    float aq[8][4];
    {
        const float* q0 = Ps + (w * 16 + r) * AT_PAD + l4 * 2;
        const float* q1 = q0 + 8 * AT_PAD;
#pragma unroll
        for (int k = 0; k < 8; k++) {
            float2 f = *(const float2*)(q0 + k * 8);
            float2 g = *(const float2*)(q1 + k * 8);
            aq[k][0] = f.x; aq[k][1] = g.x; aq[k][2] = f.y; aq[k][3] = g.y;
        }
    }
    __syncthreads();   // Q fragments extracted; Ps free for P use

    float O[8][4];
#pragma unroll
    for (int nt = 0; nt < 8; nt++)
#pragma unroll
        for (int j = 0; j < 4; j++) O[nt][j] = 0.0f;
    float m0v = -1e30f, m1v = -1e30f, l0v = 0.0f, l1v = 0.0f;

    const int tq0 = qbase + w * 16 + r;
    const int tq1 = tq0 + 8;
    const int ntiles = 2 * qt + 2;
    float* pw = Ps + (w * 16) * AT_PAD;

    for (int kt = 0; kt < ntiles; kt++) {
        const int kbase = kt * 64;
        const int buf = kt & 1;
        const float* Ksm = buf ? Kb1 : Kb0;
        const float* VTs = buf ? Vb1 : Vb0;
        const bool more = (kt + 1 < ntiles);

        // Issue async load of next tile into the other buffer (overlaps compute)
        if (more)
            at_load_kv(sb + (buf ^ 1) * koff, sb + 2 * koff + (buf ^ 1) * koff,
                       Kp, Vtp, kbase + 64, tid);

        // S = Q K^T
        float s[8][4];
#pragma unroll
        for (int nt = 0; nt < 8; nt++) {
#pragma unroll
            for (int j = 0; j < 4; j++) s[nt][j] = 0.0f;
            const float* kp = Ksm + (nt * 8 + r) * AT_PAD + l4 * 2;
#pragma unroll
            for (int k = 0; k < 8; k++) {
                float2 b = *(const float2*)(kp + k * 8);
                mma_tf32(s[nt], aq[k][0], aq[k][1], aq[k][2], aq[k][3], b.x, b.y);
            }
        }

        // scale + causal mask
        if (kbase + 63 <= qbase + w * 16) {
#pragma unroll
            for (int nt = 0; nt < 8; nt++)
#pragma unroll
                for (int j = 0; j < 4; j++) s[nt][j] *= scale;
        } else {
#pragma unroll
            for (int nt = 0; nt < 8; nt++) {
                int tk = kbase + nt * 8 + 2 * l4;
                s[nt][0] = (tk     <= tq0) ? s[nt][0] * scale : -1e30f;
                s[nt][1] = (tk + 1 <= tq0) ? s[nt][1] * scale : -1e30f;
                s[nt][2] = (tk     <= tq1) ? s[nt][2] * scale : -1e30f;
                s[nt][3] = (tk + 1 <= tq1) ? s[nt][3] * scale : -1e30f;
            }
        }

        // online softmax
        float ml0 = -1e30f, ml1 = -1e30f;
#pragma unroll
        for (int nt = 0; nt < 8; nt++) {
            ml0 = fmaxf(ml0, fmaxf(s[nt][0], s[nt][1]));
            ml1 = fmaxf(ml1, fmaxf(s[nt][2], s[nt][3]));
        }
        ml0 = fmaxf(ml0, __shfl_xor_sync(0xffffffffu, ml0, 1));
        ml0 = fmaxf(ml0, __shfl_xor_sync(0xffffffffu, ml0, 2));
        ml1 = fmaxf(ml1, __shfl_xor_sync(0xffffffffu, ml1, 1));
        ml1 = fmaxf(ml1, __shfl_xor_sync(0xffffffffu, ml1, 2));
        float mn0 = fmaxf(m0v, ml0), mn1 = fmaxf(m1v, ml1);
        float c0 = __expf(m0v - mn0), c1 = __expf(m1v - mn1);
        float ps0 = 0.0f, ps1 = 0.0f;
#pragma unroll
        for (int nt = 0; nt < 8; nt++) {
            s[nt][0] = __expf(s[nt][0] - mn0); ps0 += s[nt][0];
            s[nt][1] = __expf(s[nt][1] - mn0); ps0 += s[nt][1];
            s[nt][2] = __expf(s[nt][2] - mn1); ps1 += s[nt][2];
            s[nt][3] = __expf(s[nt][3] - mn1); ps1 += s[nt][3];
        }
        ps0 += __shfl_xor_sync(0xffffffffu, ps0, 1);
        ps0 += __shfl_xor_sync(0xffffffffu, ps0, 2);
        ps1 += __shfl_xor_sync(0xffffffffu, ps1, 1);
        ps1 += __shfl_xor_sync(0xffffffffu, ps1, 2);
        l0v = l0v * c0 + ps0; m0v = mn0;
        l1v = l1v * c1 + ps1; m1v = mn1;
#pragma unroll
        for (int nt = 0; nt < 8; nt++) {
            O[nt][0] *= c0; O[nt][1] *= c0;
            O[nt][2] *= c1; O[nt][3] *= c1;
        }

        // P -> per-warp smem (natural float2 stores), tf32-rounded
#pragma unroll
        for (int nt = 0; nt < 8; nt++) {
            *(float2*)(pw + r * AT_PAD + nt * 8 + 2 * l4)
                = make_float2(to_tf32(s[nt][0]), to_tf32(s[nt][1]));
            *(float2*)(pw + (r + 8) * AT_PAD + nt * 8 + 2 * l4)
                = make_float2(to_tf32(s[nt][2]), to_tf32(s[nt][3]));
        }
        __syncwarp();

        float pa[8][4];
        {
            const float* p0 = pw + r * AT_PAD + l4 * 2;
            const float* p1 = p0 + 8 * AT_PAD;
#pragma unroll
            for (int k = 0; k < 8; k++) {
                float2 f = *(const float2*)(p0 + k * 8);
                float2 g = *(const float2*)(p1 + k * 8);
                pa[k][0] = f.x; pa[k][1] = g.x; pa[k][2] = f.y; pa[k][3] = g.y;
            }
        }

        // O += P V
#pragma unroll
        for (int nt = 0; nt < 8; nt++) {
            const float* vp = VTs + (nt * 8 + r) * AT_PAD + l4 * 2;
#pragma unroll
            for (int k = 0; k < 8; k++) {
                float2 b = *(const float2*)(vp + k * 8);
                mma_tf32(O[nt], pa[k][0], pa[k][1], pa[k][2], pa[k][3], b.x, b.y);
            }
        }

        // Next tile's cp.async must be complete; all warps done with old buffer
        if (more) {
            asm volatile("cp.async.wait_group 0;" ::: "memory");
            __syncthreads();
        }
    }

    // Epilogue: normalize, write y permuted+tf32 for proj GEMM
    const int b = bh >> 4;
    const int h = bh & 15;
    const int hb = h * 64;
    const float inv0 = 1.0f / l0v, inv1 = 1.0f / l1v;
    float* y0 = Yg + (size_t)(b * TT + tq0) * CC;
    float* y1 = Yg + (size_t)(b * TT + tq1) * CC;
#pragma unroll
    for (int nt = 0; nt < 8; nt++) {
        int c = hb + nt * 8 + 2 * l4;
        int base = c & ~31;
        int k5 = c & 31, k51 = (c + 1) & 31;
        int p0 = (k5 & 3) * 8 + (k5 >> 2);
        int p1 = (k51 & 3) * 8 + (k51 >> 2);
        y0[base + p0] = to_tf32(O[nt][0] * inv0);
        y0[base + p1] = to_tf32(O[nt][1] * inv0);
        y1[base + p0] = to_tf32(O[nt][2] * inv1);
        y1[base + p1] = to_tf32(O[nt][3] * inv1);
    }
}

// ---------------------------------------------------------------------------
// Launch
// ---------------------------------------------------------------------------
extern "C" void kernel_launch(void* const* d_in, const int* in_sizes, int n_in,
                              void* d_out, int out_size)
{
    const float* x     = (const float*)d_in[0];
    const float* Wqkv  = (const float*)d_in[1];
    const float* bqkv  = (const float*)d_in[2];
    const float* Wproj = (const float*)d_in[3];
    const float* bproj = (const float*)d_in[4];
    float* out = (float*)d_out;
    (void)in_sizes; (void)n_in; (void)out_size;

    float *yp, *xp, *wtq, *wtp;
    cudaGetSymbolAddress((void**)&yp,  g_y);
    cudaGetSymbolAddress((void**)&xp,  g_xp);
    cudaGetSymbolAddress((void**)&wtq, g_wtq);
    cudaGetSymbolAddress((void**)&wtp, g_wtp);

    cudaFuncSetAttribute(mma_gemm<0>, cudaFuncAttributeMaxDynamicSharedMemorySize, GEMM_SMEM);
    cudaFuncSetAttribute(mma_gemm<1>, cudaFuncAttributeMaxDynamicSharedMemorySize, GEMM_SMEM);
    cudaFuncSetAttribute(attn_mma,    cudaFuncAttributeMaxDynamicSharedMemorySize, AT_SMEM);

    {
        int total4 = MROWS * CC / 4;
        prep_A<<<(total4 + 255) / 256, 256>>>(x, xp, total4, CC);
        transpose_perm<<<dim3(N_QKV / 32, CC / 32), dim3(32, 8)>>>(Wqkv, wtq, CC, N_QKV);
        transpose_perm<<<dim3(CC / 32, CC / 32), dim3(32, 8)>>>(Wproj, wtp, CC, CC);
    }

    mma_gemm<0><<<dim3(N_QKV / 128, MROWS / 128), 128, GEMM_SMEM>>>(xp, wtq, bqkv, nullptr, N_QKV);
    attn_mma<<<dim3(TT / 128, BB * HH), 256, AT_SMEM>>>(yp);
    mma_gemm<1><<<dim3(CC / 128, MROWS / 128), 128, GEMM_SMEM>>>(yp, wtp, bproj, out, CC);
}

// round 9
// speedup vs baseline: 1.3138x; 1.0756x over previous
#include <cuda_runtime.h>
#include <math.h>
#include <stdint.h>

#define BB   2
#define TT   2048
#define CC   1024
#define HH   16
#define HD   64
#define MROWS (BB*TT)        // 4096
#define N_QKV (3*CC)         // 3072

// ---------------------------------------------------------------------------
// Scratch (device globals)
// ---------------------------------------------------------------------------
__device__ __align__(1024) float g_q[BB*HH*TT*HD];   // [B,H,T,HD]  tf32
__device__ __align__(1024) float g_k[BB*HH*TT*HD];   // [B,H,T,HD]  tf32
__device__ __align__(1024) float g_v[BB*HH*TT*HD];   // [B,H,HD,T]  tf32 (TRANSPOSED)
__device__ __align__(1024) float g_y[MROWS*CC];      // attn out, natural tf32
__device__ __align__(1024) float g_xp[MROWS*CC];     // x, tf32 (natural)
__device__ __align__(1024) float g_wtq[N_QKV*CC];    // Wqkv^T, tf32 (natural)
__device__ __align__(1024) float g_wtp[CC*CC];       // Wproj^T, tf32 (natural)
__device__ int g_fq[32];                             // per-m-block QKV flags

// ---------------------------------------------------------------------------
// Helpers
// ---------------------------------------------------------------------------
__device__ __forceinline__ float to_tf32(float x) {
    float r;
    asm("cvt.rna.tf32.f32 %0, %1;" : "=f"(r) : "f"(x));
    return r;
}

__device__ __forceinline__ float ex2(float x) {
    float r;
    asm("ex2.approx.f32 %0, %1;" : "=f"(r) : "f"(x));
    return r;
}

__device__ __forceinline__ uint32_t s2u(const void* p) {
    uint32_t a;
    asm("{ .reg .u64 t; cvta.to.shared.u64 t, %1; cvt.u32.u64 %0, t; }"
        : "=r"(a) : "l"(p));
    return a;
}

__device__ __forceinline__ void cp_async16(uint32_t dst, const float* src) {
    asm volatile("cp.async.cg.shared.global [%0], [%1], 16;"
                 :: "r"(dst), "l"(src) : "memory");
}

__device__ __forceinline__ float f4e(const float4& v, int i) {
    return i == 0 ? v.x : (i == 1 ? v.y : (i == 2 ? v.z : v.w));
}

__device__ __forceinline__ void mma_tf32(float d[4], float a0, float a1,
                                         float a2, float a3, float b0, float b1)
{
    asm volatile(
        "mma.sync.aligned.m16n8k8.row.col.f32.tf32.tf32.f32 "
        "{%0,%1,%2,%3}, {%4,%5,%6,%7}, {%8,%9}, {%0,%1,%2,%3};"
        : "+f"(d[0]), "+f"(d[1]), "+f"(d[2]), "+f"(d[3])
        : "r"(__float_as_uint(a0)), "r"(__float_as_uint(a1)),
          "r"(__float_as_uint(a2)), "r"(__float_as_uint(a3)),
          "r"(__float_as_uint(b0)), "r"(__float_as_uint(b1)));
}

__device__ __forceinline__ void spin_fq(int mb) {
    while (*((volatile int*)&g_fq[mb]) < 24) __nanosleep(64);
}

// ---------------------------------------------------------------------------
// Prep kernels: tf32 rounding (natural layout; no permutes needed —
// A and B fragment k-mappings are identical, so any consistent layout works)
// ---------------------------------------------------------------------------
__global__ void prep_cvt(const float* __restrict__ in, float* __restrict__ out,
                         int total4)
{
    int i = blockIdx.x * 256 + threadIdx.x;
    if (i >= total4) return;
    float4 v = ((const float4*)in)[i];
    ((float4*)out)[i] = make_float4(to_tf32(v.x), to_tf32(v.y),
                                    to_tf32(v.z), to_tf32(v.w));
}

__global__ void transpose_nat(const float* __restrict__ in,
                              float* __restrict__ out, int R, int C)
{
    __shared__ float t[32][33];
    int c0 = blockIdx.x * 32, r0 = blockIdx.y * 32;
    int x = threadIdx.x, y = threadIdx.y;
#pragma unroll
    for (int i = 0; i < 32; i += 8)
        t[y + i][x] = in[(size_t)(r0 + y + i) * C + c0 + x];
    __syncthreads();
#pragma unroll
    for (int i = 0; i < 32; i += 8)
        out[(size_t)(c0 + y + i) * R + r0 + x] = to_tf32(t[x][y + i]);
}

// ---------------------------------------------------------------------------
// GEMM tiling constants (R7 config)
// ---------------------------------------------------------------------------
#define GSTAGES 3
#define KB      32
#define APAD    36
#define TILE_F  (128*APAD)
#define GEMM_SMEM (GSTAGES*2*TILE_F*4)

#define AT_PAD  72   // attention smem row stride (fits inside GEMM_SMEM)

__device__ __forceinline__ void g_load_stage(uint32_t sbase, int s,
                                             const float* Ag, const float* Bg,
                                             int k0, int tid)
{
    uint32_t base = sbase + (uint32_t)s * 2 * TILE_F * 4;
#pragma unroll
    for (int i = 0; i < 8; i++) {
        int f = tid + i * 128;
        int row = f >> 3, c = f & 7;
        cp_async16(base + row * (APAD * 4) + c * 16,
                   Ag + (size_t)row * CC + k0 + c * 4);
        cp_async16(base + TILE_F * 4 + row * (APAD * 4) + c * 16,
                   Bg + (size_t)row * CC + k0 + c * 4);
    }
    asm volatile("cp.async.commit_group;" ::: "memory");
}

// ---------------------------------------------------------------------------
// Mega-kernel: bids 0..767 = QKV GEMM (producers, flag release);
//              bids 768..1791 = flash attention (consumers, per-tile spin).
// ---------------------------------------------------------------------------
__global__ __launch_bounds__(128, 2)
void mega_kernel(const float* __restrict__ A, const float* __restrict__ Bt,
                 const float* __restrict__ bias, float* __restrict__ Yg)
{
    extern __shared__ __align__(16) float sm[];
    const uint32_t sbase = s2u(sm);
    const int tid = threadIdx.x;
    const int bid = blockIdx.x;
    const int lane = tid & 31;
    const int r    = lane >> 2;
    const int l4   = lane & 3;

    if (bid < 768) {
        // ================= QKV GEMM =================
        const int wid = tid >> 5;
        const int wm  = wid & 1;
        const int wn  = wid >> 1;
        const int rank = bid / 24, nblk = bid % 24;
        const int mblock = ((rank & 1) << 4) | (rank >> 1);   // batch-interleaved
        const int m0 = mblock << 7, n0 = nblk << 7;

        const float* Ag = A + (size_t)m0 * CC;
        const float* Bg = Bt + (size_t)n0 * CC;

        float acc[4][8][4];
#pragma unroll
        for (int mt = 0; mt < 4; mt++)
#pragma unroll
            for (int nt = 0; nt < 8; nt++)
#pragma unroll
                for (int j = 0; j < 4; j++) acc[mt][nt][j] = 0.0f;

        const int NIT = CC / KB;
#pragma unroll
        for (int s = 0; s < GSTAGES - 1; s++)
            g_load_stage(sbase, s, Ag, Bg, s * KB, tid);

        for (int it = 0; it < NIT; it++) {
            if (it < NIT - 1)
                asm volatile("cp.async.wait_group %0;" :: "n"(GSTAGES - 2) : "memory");
            else
                asm volatile("cp.async.wait_group 0;" ::: "memory");
            __syncthreads();

            if (it + GSTAGES - 1 < NIT)
                g_load_stage(sbase, (it + GSTAGES - 1) % GSTAGES, Ag, Bg,
                             (it + GSTAGES - 1) * KB, tid);

            const float* As = sm + (size_t)(it % GSTAGES) * 2 * TILE_F;
            const float* Bs = As + TILE_F;

#pragma unroll
            for (int hi = 0; hi < 2; hi++) {
                float4 afh[4][2];
#pragma unroll
                for (int mt = 0; mt < 4; mt++) {
                    const float* ap = As + (wm * 64 + mt * 16 + r) * APAD
                                         + l4 * 8 + hi * 4;
                    afh[mt][0] = *(const float4*)ap;
                    afh[mt][1] = *(const float4*)(ap + 8 * APAD);
                }
                float4 bfh[8];
#pragma unroll
                for (int nt = 0; nt < 8; nt++) {
                    const float* bp = Bs + (wn * 64 + nt * 8 + r) * APAD
                                         + l4 * 8 + hi * 4;
                    bfh[nt] = *(const float4*)bp;
                }
#pragma unroll
                for (int g2 = 0; g2 < 2; g2++) {
                    const int e0 = g2 * 2, e1 = e0 + 1;
#pragma unroll
                    for (int mt = 0; mt < 4; mt++) {
                        float a0 = f4e(afh[mt][0], e0);
                        float a1 = f4e(afh[mt][1], e0);
                        float a2 = f4e(afh[mt][0], e1);
                        float a3 = f4e(afh[mt][1], e1);
#pragma unroll
                        for (int nt = 0; nt < 8; nt++) {
                            float b0 = f4e(bfh[nt], e0);
                            float b1 = f4e(bfh[nt], e1);
                            mma_tf32(acc[mt][nt], a0, a1, a2, a3, b0, b1);
                        }
                    }
                }
            }
        }

        // Epilogue: bias + head scatter (q,k natural; v transposed, tf32)
#pragma unroll
        for (int mt = 0; mt < 4; mt++) {
#pragma unroll
            for (int nt = 0; nt < 8; nt++) {
                const int row = m0 + wm * 64 + mt * 16 + r;
                const int c   = n0 + wn * 64 + nt * 8 + 2 * l4;
                const float b0v = __ldg(bias + c);
                const float b1v = __ldg(bias + c + 1);
                float v00 = acc[mt][nt][0] + b0v, v01 = acc[mt][nt][1] + b1v;
                float v10 = acc[mt][nt][2] + b0v, v11 = acc[mt][nt][3] + b1v;
                const int sec = c >> 10;
                const int cs = c & 1023, h = cs >> 6, d0 = cs & 63;
                const int b  = row >> 11;
                const int t0 = row & 2047;
                const int t1 = (row + 8) & 2047;
                if (sec == 2) {
                    float* vb = g_v + ((size_t)(b * HH + h) * HD) * TT;
                    vb[(size_t)d0 * TT + t0]       = to_tf32(v00);
                    vb[(size_t)(d0 + 1) * TT + t0] = to_tf32(v01);
                    vb[(size_t)d0 * TT + t1]       = to_tf32(v10);
                    vb[(size_t)(d0 + 1) * TT + t1] = to_tf32(v11);
                } else {
                    float* basep = (sec == 0) ? g_q : g_k;
                    float* p0 = basep + (((size_t)(b * HH + h) * TT + t0) * HD + d0);
                    float* p1 = basep + (((size_t)(b * HH + h) * TT + t1) * HD + d0);
                    *(float2*)p0 = make_float2(to_tf32(v00), to_tf32(v01));
                    *(float2*)p1 = make_float2(to_tf32(v10), to_tf32(v11));
                }
            }
        }
        __syncthreads();
        __threadfence();
        if (tid == 0) atomicAdd(&g_fq[mblock], 1);
        return;
    }

    // ================= Flash attention (q-tile 64, 4 warps) =================
    {
        const int abid = bid - 768;
        const int qb   = 31 - (abid >> 5);          // heavy-first
        const int bh   = abid & 31;
        const int b    = bh >> 4, h = bh & 15;
        const int qbase = qb * 64;
        const int ntiles = qb + 1;
        const int bqoff  = b * 16;
        const int w = tid >> 5;

        float* Kb0 = sm;
        float* Kb1 = sm + 64 * AT_PAD;
        float* Vb0 = sm + 2 * 64 * AT_PAD;
        float* Vb1 = sm + 3 * 64 * AT_PAD;
        float* Ps  = sm + 4 * 64 * AT_PAD;          // [64][72]
        const uint32_t koff = (uint32_t)(64 * AT_PAD * 4);

        const float* Qp  = g_q + (size_t)bh * TT * HD;
        const float* Kp  = g_k + (size_t)bh * TT * HD;
        const float* Vtp = g_v + (size_t)bh * HD * TT;

        // wait for Q rows block + k-tiles 0/1 block
        if (tid == 0) {
            spin_fq(bqoff + (qb >> 1));
            spin_fq(bqoff);
            __threadfence();
        }
        __syncthreads();

        // issue Q staging + tile0 K/V
#pragma unroll
        for (int i = 0; i < 8; i++) {
            int f = tid + i * 128;
            int t = f >> 4, dq = f & 15;
            cp_async16(sbase + (uint32_t)(4 * 64 * AT_PAD + t * AT_PAD + dq * 4) * 4,
                       Qp + (size_t)(qbase + t) * HD + dq * 4);
        }
#pragma unroll
        for (int i = 0; i < 8; i++) {
            int f = tid + i * 128;
            int t = f >> 4, dq = f & 15;
            cp_async16(sbase + (uint32_t)(t * AT_PAD + dq * 4) * 4,
                       Kp + (size_t)t * HD + dq * 4);
            cp_async16(sbase + 2 * koff + (uint32_t)(t * AT_PAD + dq * 4) * 4,
                       Vtp + (size_t)t * TT + dq * 4);
        }
        asm volatile("cp.async.commit_group;" ::: "memory");
        asm volatile("cp.async.wait_group 0;" ::: "memory");
        __syncthreads();

        // Q fragments, pre-scaled by scale*log2e, tf32-rounded
        const float QS = 0.125f * 1.44269504089f;
        float aq[8][4];
        {
            const float* q0 = Ps + (w * 16 + r) * AT_PAD + l4 * 2;
            const float* q1 = q0 + 8 * AT_PAD;
#pragma unroll
            for (int k = 0; k < 8; k++) {
                float2 f = *(const float2*)(q0 + k * 8);
                float2 g = *(const float2*)(q1 + k * 8);
                aq[k][0] = to_tf32(f.x * QS); aq[k][1] = to_tf32(g.x * QS);
                aq[k][2] = to_tf32(f.y * QS); aq[k][3] = to_tf32(g.y * QS);
            }
        }
        __syncthreads();   // Ps now free for P

        float O[8][4];
#pragma unroll
        for (int nt = 0; nt < 8; nt++)
#pragma unroll
            for (int j = 0; j < 4; j++) O[nt][j] = 0.0f;
        float m0v = -1e30f, m1v = -1e30f, l0v = 0.0f, l1v = 0.0f;

        const int tq0 = qbase + w * 16 + r;
        const int tq1 = tq0 + 8;
        float* pw = Ps + (w * 16) * AT_PAD;

        for (int kt = 0; kt < ntiles; kt++) {
            const int kbase = kt * 64;
            const int buf = kt & 1;
            const float* Ksm = buf ? Kb1 : Kb0;
            const float* VTs = buf ? Vb1 : Vb0;
            const bool more = (kt + 1 < ntiles);

            if (more) {
                const int nb = kbase + 64;
                uint32_t kd = sbase + (uint32_t)(buf ^ 1) * koff;
                uint32_t vd = sbase + 2 * koff + (uint32_t)(buf ^ 1) * koff;
#pragma unroll
                for (int i = 0; i < 8; i++) {
                    int f = tid + i * 128;
                    int t = f >> 4, dq = f & 15;
                    cp_async16(kd + (uint32_t)(t * AT_PAD + dq * 4) * 4,
                               Kp + (size_t)(nb + t) * HD + dq * 4);
                    cp_async16(vd + (uint32_t)(t * AT_PAD + dq * 4) * 4,
                               Vtp + (size_t)t * TT + nb + dq * 4);
                }
                asm volatile("cp.async.commit_group;" ::: "memory");
            }

            // S = Q K^T (already scaled via aq)
            float s[8][4];
#pragma unroll
            for (int nt = 0; nt < 8; nt++) {
#pragma unroll
                for (int j = 0; j < 4; j++) s[nt][j] = 0.0f;
                const float* kp = Ksm + (nt * 8 + r) * AT_PAD + l4 * 2;
#pragma unroll
                for (int k = 0; k < 8; k++) {
                    float2 b2 = *(const float2*)(kp + k * 8);
                    mma_tf32(s[nt], aq[k][0], aq[k][1], aq[k][2], aq[k][3],
                             b2.x, b2.y);
                }
            }

            // causal mask (diagonal tile only)
            if (kbase + 63 > qbase + w * 16) {
#pragma unroll
                for (int nt = 0; nt < 8; nt++) {
                    int tk = kbase + nt * 8 + 2 * l4;
                    if (tk     > tq0) s[nt][0] = -1e30f;
                    if (tk + 1 > tq0) s[nt][1] = -1e30f;
                    if (tk     > tq1) s[nt][2] = -1e30f;
                    if (tk + 1 > tq1) s[nt][3] = -1e30f;
                }
            }

            // online softmax (log2 domain)
            float ml0 = -1e30f, ml1 = -1e30f;
#pragma unroll
            for (int nt = 0; nt < 8; nt++) {
                ml0 = fmaxf(ml0, fmaxf(s[nt][0], s[nt][1]));
                ml1 = fmaxf(ml1, fmaxf(s[nt][2], s[nt][3]));
            }
            ml0 = fmaxf(ml0, __shfl_xor_sync(0xffffffffu, ml0, 1));
            ml0 = fmaxf(ml0, __shfl_xor_sync(0xffffffffu, ml0, 2));
            ml1 = fmaxf(ml1, __shfl_xor_sync(0xffffffffu, ml1, 1));
            ml1 = fmaxf(ml1, __shfl_xor_sync(0xffffffffu, ml1, 2));
            float mn0 = fmaxf(m0v, ml0), mn1 = fmaxf(m1v, ml1);
            float c0 = ex2(m0v - mn0), c1 = ex2(m1v - mn1);
            float ps0 = 0.0f, ps1 = 0.0f;
#pragma unroll
            for (int nt = 0; nt < 8; nt++) {
                s[nt][0] = ex2(s[nt][0] - mn0); ps0 += s[nt][0];
                s[nt][1] = ex2(s[nt][1] - mn0); ps0 += s[nt][1];
                s[nt][2] = ex2(s[nt][2] - mn1); ps1 += s[nt][2];
                s[nt][3] = ex2(s[nt][3] - mn1); ps1 += s[nt][3];
            }
            ps0 += __shfl_xor_sync(0xffffffffu, ps0, 1);
            ps0 += __shfl_xor_sync(0xffffffffu, ps0, 2);
            ps1 += __shfl_xor_sync(0xffffffffu, ps1, 1);
            ps1 += __shfl_xor_sync(0xffffffffu, ps1, 2);
            l0v = l0v * c0 + ps0; m0v = mn0;
            l1v = l1v * c1 + ps1; m1v = mn1;
#pragma unroll
            for (int nt = 0; nt < 8; nt++) {
                O[nt][0] *= c0; O[nt][1] *= c0;
                O[nt][2] *= c1; O[nt][3] *= c1;
            }

            // P -> per-warp smem (natural), tf32-rounded
#pragma unroll
            for (int nt = 0; nt < 8; nt++) {
                *(float2*)(pw + r * AT_PAD + nt * 8 + 2 * l4)
                    = make_float2(to_tf32(s[nt][0]), to_tf32(s[nt][1]));
                *(float2*)(pw + (r + 8) * AT_PAD + nt * 8 + 2 * l4)
                    = make_float2(to_tf32(s[nt][2]), to_tf32(s[nt][3]));
            }
            __syncwarp();

            float pa[8][4];
            {
                const float* p0 = pw + r * AT_PAD + l4 * 2;
                const float* p1 = p0 + 8 * AT_PAD;
#pragma unroll
                for (int k = 0; k < 8; k++) {
                    float2 f = *(const float2*)(p0 + k * 8);
                    float2 g = *(const float2*)(p1 + k * 8);
                    pa[k][0] = f.x; pa[k][1] = g.x; pa[k][2] = f.y; pa[k][3] = g.y;
                }
            }

            // O += P V
#pragma unroll
            for (int nt = 0; nt < 8; nt++) {
                const float* vp = VTs + (nt * 8 + r) * AT_PAD + l4 * 2;
#pragma unroll
                for (int k = 0; k < 8; k++) {
                    float2 b2 = *(const float2*)(vp + k * 8);
                    mma_tf32(O[nt], pa[k][0], pa[k][1], pa[k][2], pa[k][3],
                             b2.x, b2.y);
                }
            }

            if (more) {
                asm volatile("cp.async.wait_group 0;" ::: "memory");
                if (tid == 0) {
                    if (kt + 2 < ntiles) spin_fq(bqoff + ((kt + 2) >> 1));
                    __threadfence();
                }
                __syncthreads();
            }
        }

        // Epilogue: normalize, natural tf32 y
        const int hb = h * 64;
        const float inv0 = 1.0f / l0v, inv1 = 1.0f / l1v;
        float* y0 = Yg + (size_t)(b * TT + tq0) * CC;
        float* y1 = Yg + (size_t)(b * TT + tq1) * CC;
#pragma unroll
        for (int nt = 0; nt < 8; nt++) {
            int c = hb + nt * 8 + 2 * l4;
            *(float2*)(y0 + c) = make_float2(to_tf32(O[nt][0] * inv0),
                                             to_tf32(O[nt][1] * inv0));
            *(float2*)(y1 + c) = make_float2(to_tf32(O[nt][2] * inv1),
                                             to_tf32(O[nt][3] * inv1));
        }
    }
}

// ---------------------------------------------------------------------------
// Proj GEMM (R7 config, MODE 1 only)
// ---------------------------------------------------------------------------
__global__ __launch_bounds__(128, 2)
void proj_gemm(const float* __restrict__ A, const float* __restrict__ Bt,
               const float* __restrict__ bias, float* __restrict__ Cout, int Nn)
{
    extern __shared__ __align__(16) float sm[];
    const uint32_t sbase = s2u(sm);
    const int tid  = threadIdx.x;
    const int lane = tid & 31;
    const int wid  = tid >> 5;
    const int wm   = wid & 1;
    const int wn   = wid >> 1;
    const int r    = lane >> 2;
    const int l4   = lane & 3;
    const int m0 = blockIdx.y * 128;
    const int n0 = blockIdx.x * 128;

    const float* Ag = A + (size_t)m0 * CC;
    const float* Bg = Bt + (size_t)n0 * CC;

    float acc[4][8][4];
#pragma unroll
    for (int mt = 0; mt < 4; mt++)
#pragma unroll
        for (int nt = 0; nt < 8; nt++)
#pragma unroll
            for (int j = 0; j < 4; j++) acc[mt][nt][j] = 0.0f;

    const int NIT = CC / KB;
#pragma unroll
    for (int s = 0; s < GSTAGES - 1; s++)
        g_load_stage(sbase, s, Ag, Bg, s * KB, tid);

    for (int it = 0; it < NIT; it++) {
        if (it < NIT - 1)
            asm volatile("cp.async.wait_group %0;" :: "n"(GSTAGES - 2) : "memory");
        else
            asm volatile("cp.async.wait_group 0;" ::: "memory");
        __syncthreads();

        if (it + GSTAGES - 1 < NIT)
            g_load_stage(sbase, (it + GSTAGES - 1) % GSTAGES, Ag, Bg,
                         (it + GSTAGES - 1) * KB, tid);

        const float* As = sm + (size_t)(it % GSTAGES) * 2 * TILE_F;
        const float* Bs = As + TILE_F;

#pragma unroll
        for (int hi = 0; hi < 2; hi++) {
            float4 afh[4][2];
#pragma unroll
            for (int mt = 0; mt < 4; mt++) {
                const float* ap = As + (wm * 64 + mt * 16 + r) * APAD
                                     + l4 * 8 + hi * 4;
                afh[mt][0] = *(const float4*)ap;
                afh[mt][1] = *(const float4*)(ap + 8 * APAD);
            }
            float4 bfh[8];
#pragma unroll
            for (int nt = 0; nt < 8; nt++) {
                const float* bp = Bs + (wn * 64 + nt * 8 + r) * APAD
                                     + l4 * 8 + hi * 4;
                bfh[nt] = *(const float4*)bp;
            }
#pragma unroll
            for (int g2 = 0; g2 < 2; g2++) {
                const int e0 = g2 * 2, e1 = e0 + 1;
#pragma unroll
                for (int mt = 0; mt < 4; mt++) {
                    float a0 = f4e(afh[mt][0], e0);
                    float a1 = f4e(afh[mt][1], e0);
                    float a2 = f4e(afh[mt][0], e1);
                    float a3 = f4e(afh[mt][1], e1);
#pragma unroll
                    for (int nt = 0; nt < 8; nt++) {
                        float b0 = f4e(bfh[nt], e0);
                        float b1 = f4e(bfh[nt], e1);
                        mma_tf32(acc[mt][nt], a0, a1, a2, a3, b0, b1);
                    }
                }
            }
        }
    }

#pragma unroll
    for (int mt = 0; mt < 4; mt++) {
#pragma unroll
        for (int nt = 0; nt < 8; nt++) {
            const int row = m0 + wm * 64 + mt * 16 + r;
            const int c   = n0 + wn * 64 + nt * 8 + 2 * l4;
            const float b0v = __ldg(bias + c);
            const float b1v = __ldg(bias + c + 1);
            *(float2*)(Cout + (size_t)row * Nn + c)
                = make_float2(acc[mt][nt][0] + b0v, acc[mt][nt][1] + b1v);
            *(float2*)(Cout + (size_t)(row + 8) * Nn + c)
                = make_float2(acc[mt][nt][2] + b0v, acc[mt][nt][3] + b1v);
        }
    }
}

// ---------------------------------------------------------------------------
// Launch
// ---------------------------------------------------------------------------
extern "C" void kernel_launch(void* const* d_in, const int* in_sizes, int n_in,
                              void* d_out, int out_size)
{
    const float* x     = (const float*)d_in[0];
    const float* Wqkv  = (const float*)d_in[1];
    const float* bqkv  = (const float*)d_in[2];
    const float* Wproj = (const float*)d_in[3];
    const float* bproj = (const float*)d_in[4];
    float* out = (float*)d_out;
    (void)in_sizes; (void)n_in; (void)out_size;

    float *yp, *xp, *wtq, *wtp;
    int* fq;
    cudaGetSymbolAddress((void**)&yp,  g_y);
    cudaGetSymbolAddress((void**)&xp,  g_xp);
    cudaGetSymbolAddress((void**)&wtq, g_wtq);
    cudaGetSymbolAddress((void**)&wtp, g_wtp);
    cudaGetSymbolAddress((void**)&fq,  g_fq);

    cudaFuncSetAttribute(mega_kernel, cudaFuncAttributeMaxDynamicSharedMemorySize, GEMM_SMEM);
    cudaFuncSetAttribute(proj_gemm,   cudaFuncAttributeMaxDynamicSharedMemorySize, GEMM_SMEM);

    cudaMemsetAsync(fq, 0, 32 * sizeof(int));

    {
        int total4 = MROWS * CC / 4;
        prep_cvt<<<(total4 + 255) / 256, 256>>>(x, xp, total4);
        transpose_nat<<<dim3(N_QKV / 32, CC / 32), dim3(32, 8)>>>(Wqkv, wtq, CC, N_QKV);
        transpose_nat<<<dim3(CC / 32, CC / 32), dim3(32, 8)>>>(Wproj, wtp, CC, CC);
    }

    // Fused QKV GEMM + flash attention (producer/consumer via flags)
    mega_kernel<<<768 + 1024, 128, GEMM_SMEM>>>(xp, wtq, bqkv, yp);

    // Output projection
    proj_gemm<<<dim3(CC / 128, MROWS / 128), 128, GEMM_SMEM>>>(yp, wtp, bproj, out, CC);
}

// round 10
// speedup vs baseline: 1.3151x; 1.0010x over previous
#include <cuda_runtime.h>
#include <math.h>
#include <stdint.h>

#define BB   2
#define TT   2048
#define CC   1024
#define HH   16
#define HD   64
#define MROWS (BB*TT)        // 4096
#define N_QKV (3*CC)         // 3072

// ---------------------------------------------------------------------------
// Scratch (device globals)
// ---------------------------------------------------------------------------
__device__ __align__(1024) float g_q[BB*HH*TT*HD];   // [B,H,T,HD]  tf32
__device__ __align__(1024) float g_k[BB*HH*TT*HD];   // [B,H,T,HD]  tf32
__device__ __align__(1024) float g_v[BB*HH*TT*HD];   // [B,H,HD,T]  tf32 (TRANSPOSED)
__device__ __align__(1024) float g_y[MROWS*CC];      // attn out, natural tf32
__device__ __align__(1024) float g_xp[MROWS*CC];     // x, tf32 (natural)
__device__ __align__(1024) float g_wtq[N_QKV*CC];    // Wqkv^T, tf32 (natural)
__device__ __align__(1024) float g_wtp[CC*CC];       // Wproj^T, tf32 (natural)
__device__ int g_fq[32];                             // per-m-block QKV flags
__device__ int g_fy[32];                             // per-m-block attn-out flags

// ---------------------------------------------------------------------------
// Helpers
// ---------------------------------------------------------------------------
__device__ __forceinline__ float to_tf32(float x) {
    float r;
    asm("cvt.rna.tf32.f32 %0, %1;" : "=f"(r) : "f"(x));
    return r;
}

__device__ __forceinline__ float ex2(float x) {
    float r;
    asm("ex2.approx.f32 %0, %1;" : "=f"(r) : "f"(x));
    return r;
}

__device__ __forceinline__ uint32_t s2u(const void* p) {
    uint32_t a;
    asm("{ .reg .u64 t; cvta.to.shared.u64 t, %1; cvt.u32.u64 %0, t; }"
        : "=r"(a) : "l"(p));
    return a;
}

__device__ __forceinline__ void cp_async16(uint32_t dst, const float* src) {
    asm volatile("cp.async.cg.shared.global [%0], [%1], 16;"
                 :: "r"(dst), "l"(src) : "memory");
}

__device__ __forceinline__ float f4e(const float4& v, int i) {
    return i == 0 ? v.x : (i == 1 ? v.y : (i == 2 ? v.z : v.w));
}

__device__ __forceinline__ void mma_tf32(float d[4], float a0, float a1,
                                         float a2, float a3, float b0, float b1)
{
    asm volatile(
        "mma.sync.aligned.m16n8k8.row.col.f32.tf32.tf32.f32 "
        "{%0,%1,%2,%3}, {%4,%5,%6,%7}, {%8,%9}, {%0,%1,%2,%3};"
        : "+f"(d[0]), "+f"(d[1]), "+f"(d[2]), "+f"(d[3])
        : "r"(__float_as_uint(a0)), "r"(__float_as_uint(a1)),
          "r"(__float_as_uint(a2)), "r"(__float_as_uint(a3)),
          "r"(__float_as_uint(b0)), "r"(__float_as_uint(b1)));
}

__device__ __forceinline__ void spin_flag(int* flags, int idx, int target) {
    while (*((volatile int*)&flags[idx]) < target) __nanosleep(64);
}

// ---------------------------------------------------------------------------
// Prep kernels: tf32 rounding, natural layout
// ---------------------------------------------------------------------------
__global__ void prep_cvt(const float* __restrict__ in, float* __restrict__ out,
                         int total4)
{
    int i = blockIdx.x * 256 + threadIdx.x;
    if (i >= total4) return;
    float4 v = ((const float4*)in)[i];
    ((float4*)out)[i] = make_float4(to_tf32(v.x), to_tf32(v.y),
                                    to_tf32(v.z), to_tf32(v.w));
}

__global__ void transpose_nat(const float* __restrict__ in,
                              float* __restrict__ out, int R, int C)
{
    __shared__ float t[32][33];
    int c0 = blockIdx.x * 32, r0 = blockIdx.y * 32;
    int x = threadIdx.x, y = threadIdx.y;
#pragma unroll
    for (int i = 0; i < 32; i += 8)
        t[y + i][x] = in[(size_t)(r0 + y + i) * C + c0 + x];
    __syncthreads();
#pragma unroll
    for (int i = 0; i < 32; i += 8)
        out[(size_t)(c0 + y + i) * R + r0 + x] = to_tf32(t[x][y + i]);
}

// ---------------------------------------------------------------------------
// GEMM tiling constants (R7 config)
// ---------------------------------------------------------------------------
#define GSTAGES 3
#define KB      32
#define APAD    36
#define TILE_F  (128*APAD)
#define GEMM_SMEM (GSTAGES*2*TILE_F*4)

#define AT_PAD  72   // attention smem row stride (fits inside GEMM_SMEM)

__device__ __forceinline__ void g_load_stage(uint32_t sbase, int s,
                                             const float* Ag, const float* Bg,
                                             int k0, int tid)
{
    uint32_t base = sbase + (uint32_t)s * 2 * TILE_F * 4;
#pragma unroll
    for (int i = 0; i < 8; i++) {
        int f = tid + i * 128;
        int row = f >> 3, c = f & 7;
        cp_async16(base + row * (APAD * 4) + c * 16,
                   Ag + (size_t)row * CC + k0 + c * 4);
        cp_async16(base + TILE_F * 4 + row * (APAD * 4) + c * 16,
                   Bg + (size_t)row * CC + k0 + c * 4);
    }
    asm volatile("cp.async.commit_group;" ::: "memory");
}

// GEMM mainloop: accumulates 128x128 tile into acc. Shared by QKV and proj.
__device__ __forceinline__ void gemm_mainloop(float* sm, uint32_t sbase,
                                              const float* Ag, const float* Bg,
                                              int tid, int wm, int wn,
                                              int r, int l4,
                                              float acc[4][8][4])
{
    const int NIT = CC / KB;
#pragma unroll
    for (int s = 0; s < GSTAGES - 1; s++)
        g_load_stage(sbase, s, Ag, Bg, s * KB, tid);

    for (int it = 0; it < NIT; it++) {
        if (it < NIT - 1)
            asm volatile("cp.async.wait_group %0;" :: "n"(GSTAGES - 2) : "memory");
        else
            asm volatile("cp.async.wait_group 0;" ::: "memory");
        __syncthreads();

        if (it + GSTAGES - 1 < NIT)
            g_load_stage(sbase, (it + GSTAGES - 1) % GSTAGES, Ag, Bg,
                         (it + GSTAGES - 1) * KB, tid);

        const float* As = sm + (size_t)(it % GSTAGES) * 2 * TILE_F;
        const float* Bs = As + TILE_F;

#pragma unroll
        for (int hi = 0; hi < 2; hi++) {
            float4 afh[4][2];
#pragma unroll
            for (int mt = 0; mt < 4; mt++) {
                const float* ap = As + (wm * 64 + mt * 16 + r) * APAD
                                     + l4 * 8 + hi * 4;
                afh[mt][0] = *(const float4*)ap;
                afh[mt][1] = *(const float4*)(ap + 8 * APAD);
            }
            float4 bfh[8];
#pragma unroll
            for (int nt = 0; nt < 8; nt++) {
                const float* bp = Bs + (wn * 64 + nt * 8 + r) * APAD
                                     + l4 * 8 + hi * 4;
                bfh[nt] = *(const float4*)bp;
            }
#pragma unroll
            for (int g2 = 0; g2 < 2; g2++) {
                const int e0 = g2 * 2, e1 = e0 + 1;
#pragma unroll
                for (int mt = 0; mt < 4; mt++) {
                    float a0 = f4e(afh[mt][0], e0);
                    float a1 = f4e(afh[mt][1], e0);
                    float a2 = f4e(afh[mt][0], e1);
                    float a3 = f4e(afh[mt][1], e1);
#pragma unroll
                    for (int nt = 0; nt < 8; nt++) {
                        float b0 = f4e(bfh[nt], e0);
                        float b1 = f4e(bfh[nt], e1);
                        mma_tf32(acc[mt][nt], a0, a1, a2, a3, b0, b1);
                    }
                }
            }
        }
    }
}

// ---------------------------------------------------------------------------
// Mega-kernel:
//   bids    0.. 767 : QKV GEMM (producers, release g_fq)
//   bids  768..1791 : flash attention (consume g_fq, release g_fy)
//   bids 1792..2047 : proj GEMM (consume g_fy)
// ---------------------------------------------------------------------------
__global__ __launch_bounds__(128, 2)
void mega_kernel(const float* __restrict__ A, const float* __restrict__ Bt,
                 const float* __restrict__ bias, float* __restrict__ Yg,
                 const float* __restrict__ Wp, const float* __restrict__ bp,
                 float* __restrict__ Out)
{
    extern __shared__ __align__(16) float sm[];
    const uint32_t sbase = s2u(sm);
    const int tid = threadIdx.x;
    const int bid = blockIdx.x;
    const int lane = tid & 31;
    const int r    = lane >> 2;
    const int l4   = lane & 3;

    if (bid < 768) {
        // ================= QKV GEMM =================
        const int wid = tid >> 5;
        const int wm  = wid & 1;
        const int wn  = wid >> 1;
        const int rank = bid / 24, nblk = bid % 24;
        const int mblock = ((rank & 1) << 4) | (rank >> 1);   // batch-interleaved
        const int m0 = mblock << 7, n0 = nblk << 7;

        float acc[4][8][4];
#pragma unroll
        for (int mt = 0; mt < 4; mt++)
#pragma unroll
            for (int nt = 0; nt < 8; nt++)
#pragma unroll
                for (int j = 0; j < 4; j++) acc[mt][nt][j] = 0.0f;

        gemm_mainloop(sm, sbase, A + (size_t)m0 * CC, Bt + (size_t)n0 * CC,
                      tid, wm, wn, r, l4, acc);

        // Epilogue: bias + head scatter (q,k natural; v transposed, tf32)
#pragma unroll
        for (int mt = 0; mt < 4; mt++) {
#pragma unroll
            for (int nt = 0; nt < 8; nt++) {
                const int row = m0 + wm * 64 + mt * 16 + r;
                const int c   = n0 + wn * 64 + nt * 8 + 2 * l4;
                const float b0v = __ldg(bias + c);
                const float b1v = __ldg(bias + c + 1);
                float v00 = acc[mt][nt][0] + b0v, v01 = acc[mt][nt][1] + b1v;
                float v10 = acc[mt][nt][2] + b0v, v11 = acc[mt][nt][3] + b1v;
                const int sec = c >> 10;
                const int cs = c & 1023, h = cs >> 6, d0 = cs & 63;
                const int b  = row >> 11;
                const int t0 = row & 2047;
                const int t1 = (row + 8) & 2047;
                if (sec == 2) {
                    float* vb = g_v + ((size_t)(b * HH + h) * HD) * TT;
                    vb[(size_t)d0 * TT + t0]       = to_tf32(v00);
                    vb[(size_t)(d0 + 1) * TT + t0] = to_tf32(v01);
                    vb[(size_t)d0 * TT + t1]       = to_tf32(v10);
                    vb[(size_t)(d0 + 1) * TT + t1] = to_tf32(v11);
                } else {
                    float* basep = (sec == 0) ? g_q : g_k;
                    float* p0 = basep + (((size_t)(b * HH + h) * TT + t0) * HD + d0);
                    float* p1 = basep + (((size_t)(b * HH + h) * TT + t1) * HD + d0);
                    *(float2*)p0 = make_float2(to_tf32(v00), to_tf32(v01));
                    *(float2*)p1 = make_float2(to_tf32(v10), to_tf32(v11));
                }
            }
        }
        __syncthreads();
        __threadfence();
        if (tid == 0) atomicAdd(&g_fq[mblock], 1);
        return;
    }

    if (bid >= 1792) {
        // ================= Proj GEMM (consumes g_fy) =================
        const int pbid = bid - 1792;                // 0..255
        const int wid = tid >> 5;
        const int wm  = wid & 1;
        const int wn  = wid >> 1;
        const int rank = pbid >> 3, nblk = pbid & 7;
        const int mb_w = 15 - (rank >> 1);          // heavy-first
        const int b    = rank & 1;
        const int mblock = b * 16 + mb_w;
        const int m0 = mblock << 7, n0 = nblk << 7;

        if (tid == 0) {
            spin_flag(g_fy, mblock, 32);
            __threadfence();
        }
        __syncthreads();

        float acc[4][8][4];
#pragma unroll
        for (int mt = 0; mt < 4; mt++)
#pragma unroll
            for (int nt = 0; nt < 8; nt++)
#pragma unroll
                for (int j = 0; j < 4; j++) acc[mt][nt][j] = 0.0f;

        gemm_mainloop(sm, sbase, Yg + (size_t)m0 * CC, Wp + (size_t)n0 * CC,
                      tid, wm, wn, r, l4, acc);

#pragma unroll
        for (int mt = 0; mt < 4; mt++) {
#pragma unroll
            for (int nt = 0; nt < 8; nt++) {
                const int row = m0 + wm * 64 + mt * 16 + r;
                const int c   = n0 + wn * 64 + nt * 8 + 2 * l4;
                const float b0v = __ldg(bp + c);
                const float b1v = __ldg(bp + c + 1);
                *(float2*)(Out + (size_t)row * CC + c)
                    = make_float2(acc[mt][nt][0] + b0v, acc[mt][nt][1] + b1v);
                *(float2*)(Out + (size_t)(row + 8) * CC + c)
                    = make_float2(acc[mt][nt][2] + b0v, acc[mt][nt][3] + b1v);
            }
        }
        return;
    }

    // ================= Flash attention (q-tile 64, 4 warps) =================
    {
        const int abid = bid - 768;
        const int qb   = 31 - (abid >> 5);          // heavy-first
        const int bh   = abid & 31;
        const int b    = bh >> 4, h = bh & 15;
        const int qbase = qb * 64;
        const int ntiles = qb + 1;
        const int bqoff  = b * 16;
        const int w = tid >> 5;

        float* Kb0 = sm;
        float* Kb1 = sm + 64 * AT_PAD;
        float* Vb0 = sm + 2 * 64 * AT_PAD;
        float* Vb1 = sm + 3 * 64 * AT_PAD;
        float* Ps  = sm + 4 * 64 * AT_PAD;          // [64][72]
        const uint32_t koff = (uint32_t)(64 * AT_PAD * 4);

        const float* Qp  = g_q + (size_t)bh * TT * HD;
        const float* Kp  = g_k + (size_t)bh * TT * HD;
        const float* Vtp = g_v + (size_t)bh * HD * TT;

        if (tid == 0) {
            spin_flag(g_fq, bqoff + (qb >> 1), 24);
            spin_flag(g_fq, bqoff, 24);
            __threadfence();
        }
        __syncthreads();

        // issue Q staging + tile0 K/V
#pragma unroll
        for (int i = 0; i < 8; i++) {
            int f = tid + i * 128;
            int t = f >> 4, dq = f & 15;
            cp_async16(sbase + (uint32_t)(4 * 64 * AT_PAD + t * AT_PAD + dq * 4) * 4,
                       Qp + (size_t)(qbase + t) * HD + dq * 4);
        }
#pragma unroll
        for (int i = 0; i < 8; i++) {
            int f = tid + i * 128;
            int t = f >> 4, dq = f & 15;
            cp_async16(sbase + (uint32_t)(t * AT_PAD + dq * 4) * 4,
                       Kp + (size_t)t * HD + dq * 4);
            cp_async16(sbase + 2 * koff + (uint32_t)(t * AT_PAD + dq * 4) * 4,
                       Vtp + (size_t)t * TT + dq * 4);
        }
        asm volatile("cp.async.commit_group;" ::: "memory");
        asm volatile("cp.async.wait_group 0;" ::: "memory");
        __syncthreads();

        // Q fragments, pre-scaled by scale*log2e, tf32-rounded
        const float QS = 0.125f * 1.44269504089f;
        float aq[8][4];
        {
            const float* q0 = Ps + (w * 16 + r) * AT_PAD + l4 * 2;
            const float* q1 = q0 + 8 * AT_PAD;
#pragma unroll
            for (int k = 0; k < 8; k++) {
                float2 f = *(const float2*)(q0 + k * 8);
                float2 g = *(const float2*)(q1 + k * 8);
                aq[k][0] = to_tf32(f.x * QS); aq[k][1] = to_tf32(g.x * QS);
                aq[k][2] = to_tf32(f.y * QS); aq[k][3] = to_tf32(g.y * QS);
            }
        }
        __syncthreads();   // Ps now free for P

        float O[8][4];
#pragma unroll
        for (int nt = 0; nt < 8; nt++)
#pragma unroll
            for (int j = 0; j < 4; j++) O[nt][j] = 0.0f;
        float m0v = -1e30f, m1v = -1e30f, l0v = 0.0f, l1v = 0.0f;

        const int tq0 = qbase + w * 16 + r;
        const int tq1 = tq0 + 8;
        float* pw = Ps + (w * 16) * AT_PAD;

        for (int kt = 0; kt < ntiles; kt++) {
            const int kbase = kt * 64;
            const int buf = kt & 1;
            const float* Ksm = buf ? Kb1 : Kb0;
            const float* VTs = buf ? Vb1 : Vb0;
            const bool more = (kt + 1 < ntiles);

            if (more) {
                const int nb = kbase + 64;
                uint32_t kd = sbase + (uint32_t)(buf ^ 1) * koff;
                uint32_t vd = sbase + 2 * koff + (uint32_t)(buf ^ 1) * koff;
#pragma unroll
                for (int i = 0; i < 8; i++) {
                    int f = tid + i * 128;
                    int t = f >> 4, dq = f & 15;
                    cp_async16(kd + (uint32_t)(t * AT_PAD + dq * 4) * 4,
                               Kp + (size_t)(nb + t) * HD + dq * 4);
                    cp_async16(vd + (uint32_t)(t * AT_PAD + dq * 4) * 4,
                               Vtp + (size_t)t * TT + nb + dq * 4);
                }
                asm volatile("cp.async.commit_group;" ::: "memory");
            }

            // S = Q K^T (already scaled via aq)
            float s[8][4];
#pragma unroll
            for (int nt = 0; nt < 8; nt++) {
#pragma unroll
                for (int j = 0; j < 4; j++) s[nt][j] = 0.0f;
                const float* kp = Ksm + (nt * 8 + r) * AT_PAD + l4 * 2;
#pragma unroll
                for (int k = 0; k < 8; k++) {
                    float2 b2 = *(const float2*)(kp + k * 8);
                    mma_tf32(s[nt], aq[k][0], aq[k][1], aq[k][2], aq[k][3],
                             b2.x, b2.y);
                }
            }

            // causal mask (diagonal tile only)
            if (kbase + 63 > qbase + w * 16) {
#pragma unroll
                for (int nt = 0; nt < 8; nt++) {
                    int tk = kbase + nt * 8 + 2 * l4;
                    if (tk     > tq0) s[nt][0] = -1e30f;
                    if (tk + 1 > tq0) s[nt][1] = -1e30f;
                    if (tk     > tq1) s[nt][2] = -1e30f;
                    if (tk + 1 > tq1) s[nt][3] = -1e30f;
                }
            }

            // online softmax (log2 domain)
            float ml0 = -1e30f, ml1 = -1e30f;
#pragma unroll
            for (int nt = 0; nt < 8; nt++) {
                ml0 = fmaxf(ml0, fmaxf(s[nt][0], s[nt][1]));
                ml1 = fmaxf(ml1, fmaxf(s[nt][2], s[nt][3]));
            }
            ml0 = fmaxf(ml0, __shfl_xor_sync(0xffffffffu, ml0, 1));
            ml0 = fmaxf(ml0, __shfl_xor_sync(0xffffffffu, ml0, 2));
            ml1 = fmaxf(ml1, __shfl_xor_sync(0xffffffffu, ml1, 1));
            ml1 = fmaxf(ml1, __shfl_xor_sync(0xffffffffu, ml1, 2));
            float mn0 = fmaxf(m0v, ml0), mn1 = fmaxf(m1v, ml1);
            float c0 = ex2(m0v - mn0), c1 = ex2(m1v - mn1);
            float ps0 = 0.0f, ps1 = 0.0f;
#pragma unroll
            for (int nt = 0; nt < 8; nt++) {
                s[nt][0] = ex2(s[nt][0] - mn0); ps0 += s[nt][0];
                s[nt][1] = ex2(s[nt][1] - mn0); ps0 += s[nt][1];
                s[nt][2] = ex2(s[nt][2] - mn1); ps1 += s[nt][2];
                s[nt][3] = ex2(s[nt][3] - mn1); ps1 += s[nt][3];
            }
            ps0 += __shfl_xor_sync(0xffffffffu, ps0, 1);
            ps0 += __shfl_xor_sync(0xffffffffu, ps0, 2);
            ps1 += __shfl_xor_sync(0xffffffffu, ps1, 1);
            ps1 += __shfl_xor_sync(0xffffffffu, ps1, 2);
            l0v = l0v * c0 + ps0; m0v = mn0;
            l1v = l1v * c1 + ps1; m1v = mn1;
#pragma unroll
            for (int nt = 0; nt < 8; nt++) {
                O[nt][0] *= c0; O[nt][1] *= c0;
                O[nt][2] *= c1; O[nt][3] *= c1;
            }

            // P -> per-warp smem (natural), tf32-rounded
#pragma unroll
            for (int nt = 0; nt < 8; nt++) {
                *(float2*)(pw + r * AT_PAD + nt * 8 + 2 * l4)
                    = make_float2(to_tf32(s[nt][0]), to_tf32(s[nt][1]));
                *(float2*)(pw + (r + 8) * AT_PAD + nt * 8 + 2 * l4)
                    = make_float2(to_tf32(s[nt][2]), to_tf32(s[nt][3]));
            }
            __syncwarp();

            float pa[8][4];
            {
                const float* p0 = pw + r * AT_PAD + l4 * 2;
                const float* p1 = p0 + 8 * AT_PAD;
#pragma unroll
                for (int k = 0; k < 8; k++) {
                    float2 f = *(const float2*)(p0 + k * 8);
                    float2 g = *(const float2*)(p1 + k * 8);
                    pa[k][0] = f.x; pa[k][1] = g.x; pa[k][2] = f.y; pa[k][3] = g.y;
                }
            }

            // O += P V
#pragma unroll
            for (int nt = 0; nt < 8; nt++) {
                const float* vp = VTs + (nt * 8 + r) * AT_PAD + l4 * 2;
#pragma unroll
                for (int k = 0; k < 8; k++) {
                    float2 b2 = *(const float2*)(vp + k * 8);
                    mma_tf32(O[nt], pa[k][0], pa[k][1], pa[k][2], pa[k][3],
                             b2.x, b2.y);
                }
            }

            if (more) {
                asm volatile("cp.async.wait_group 0;" ::: "memory");
                if (tid == 0) {
                    if (kt + 2 < ntiles) spin_flag(g_fq, bqoff + ((kt + 2) >> 1), 24);
                    __threadfence();
                }
                __syncthreads();
            }
        }

        // Epilogue: normalize, natural tf32 y, then release g_fy
        const int hb = h * 64;
        const float inv0 = 1.0f / l0v, inv1 = 1.0f / l1v;
        float* y0 = Yg + (size_t)(b * TT + tq0) * CC;
        float* y1 = Yg + (size_t)(b * TT + tq1) * CC;
#pragma unroll
        for (int nt = 0; nt < 8; nt++) {
            int c = hb + nt * 8 + 2 * l4;
            *(float2*)(y0 + c) = make_float2(to_tf32(O[nt][0] * inv0),
                                             to_tf32(O[nt][1] * inv0));
            *(float2*)(y1 + c) = make_float2(to_tf32(O[nt][2] * inv1),
                                             to_tf32(O[nt][3] * inv1));
        }
        __syncthreads();
        __threadfence();
        if (tid == 0) atomicAdd(&g_fy[b * 16 + (qb >> 1)], 1);
    }
}

// ---------------------------------------------------------------------------
// Launch
// ---------------------------------------------------------------------------
extern "C" void kernel_launch(void* const* d_in, const int* in_sizes, int n_in,
                              void* d_out, int out_size)
{
    const float* x     = (const float*)d_in[0];
    const float* Wqkv  = (const float*)d_in[1];
    const float* bqkv  = (const float*)d_in[2];
    const float* Wproj = (const float*)d_in[3];
    const float* bproj = (const float*)d_in[4];
    float* out = (float*)d_out;
    (void)in_sizes; (void)n_in; (void)out_size;

    float *yp, *xp, *wtq, *wtp;
    int *fq, *fy;
    cudaGetSymbolAddress((void**)&yp,  g_y);
    cudaGetSymbolAddress((void**)&xp,  g_xp);
    cudaGetSymbolAddress((void**)&wtq, g_wtq);
    cudaGetSymbolAddress((void**)&wtp, g_wtp);
    cudaGetSymbolAddress((void**)&fq,  g_fq);
    cudaGetSymbolAddress((void**)&fy,  g_fy);

    cudaFuncSetAttribute(mega_kernel, cudaFuncAttributeMaxDynamicSharedMemorySize, GEMM_SMEM);

    cudaMemsetAsync(fq, 0, 32 * sizeof(int));
    cudaMemsetAsync(fy, 0, 32 * sizeof(int));

    {
        int total4 = MROWS * CC / 4;
        prep_cvt<<<(total4 + 255) / 256, 256>>>(x, xp, total4);
        transpose_nat<<<dim3(N_QKV / 32, CC / 32), dim3(32, 8)>>>(Wqkv, wtq, CC, N_QKV);
        transpose_nat<<<dim3(CC / 32, CC / 32), dim3(32, 8)>>>(Wproj, wtp, CC, CC);
    }

    // Fully fused: QKV GEMM -> attention -> proj GEMM via device-side flags
    mega_kernel<<<768 + 1024 + 256, 128, GEMM_SMEM>>>(xp, wtq, bqkv, yp,
                                                      wtp, bproj, out);
}

// round 11
// speedup vs baseline: 2.2288x; 1.6948x over previous
#include <cuda_runtime.h>
#include <cuda_fp16.h>
#include <math.h>
#include <stdint.h>

#define BB   2
#define TT   2048
#define CC   1024
#define HH   16
#define HD   64
#define MROWS (BB*TT)        // 4096
#define N_QKV (3*CC)         // 3072

// ---------------------------------------------------------------------------
// Scratch (device globals) — all fp16 now
// ---------------------------------------------------------------------------
__device__ __align__(1024) __half g_q[BB*HH*TT*HD];   // [B,H,T,HD], pre-scaled by 0.125*log2e
__device__ __align__(1024) __half g_k[BB*HH*TT*HD];   // [B,H,T,HD]
__device__ __align__(1024) __half g_v[BB*HH*TT*HD];   // [B,H,HD,T]  (TRANSPOSED)
__device__ __align__(1024) __half g_y[MROWS*CC];      // attn out
__device__ __align__(1024) __half g_xp[MROWS*CC];     // x
__device__ __align__(1024) __half g_wtq[N_QKV*CC];    // Wqkv^T
__device__ __align__(1024) __half g_wtp[CC*CC];       // Wproj^T
__device__ int g_fq[32];                              // per-m-block QKV flags
__device__ int g_fy[32];                              // per-m-block attn-out flags

// ---------------------------------------------------------------------------
// Helpers
// ---------------------------------------------------------------------------
__device__ __forceinline__ float ex2(float x) {
    float r;
    asm("ex2.approx.f32 %0, %1;" : "=f"(r) : "f"(x));
    return r;
}

__device__ __forceinline__ uint32_t pack_h2(float lo, float hi) {
    uint32_t r;
    asm("cvt.rn.f16x2.f32 %0, %1, %2;" : "=r"(r) : "f"(hi), "f"(lo));
    return r;
}

__device__ __forceinline__ uint32_t s2u(const void* p) {
    uint32_t a;
    asm("{ .reg .u64 t; cvta.to.shared.u64 t, %1; cvt.u32.u64 %0, t; }"
        : "=r"(a) : "l"(p));
    return a;
}

__device__ __forceinline__ void cp_async16(uint32_t dst, const void* src) {
    asm volatile("cp.async.cg.shared.global [%0], [%1], 16;"
                 :: "r"(dst), "l"(src) : "memory");
}

// fp16 mma: D(16x8,f32) += A(16x16,f16) * B(16x8,f16)  [row.col]
__device__ __forceinline__ void mma_f16(float d[4], uint32_t a0, uint32_t a1,
                                        uint32_t a2, uint32_t a3,
                                        uint32_t b0, uint32_t b1)
{
    asm volatile(
        "mma.sync.aligned.m16n8k16.row.col.f32.f16.f16.f32 "
        "{%0,%1,%2,%3}, {%4,%5,%6,%7}, {%8,%9}, {%0,%1,%2,%3};"
        : "+f"(d[0]), "+f"(d[1]), "+f"(d[2]), "+f"(d[3])
        : "r"(a0), "r"(a1), "r"(a2), "r"(a3), "r"(b0), "r"(b1));
}

__device__ __forceinline__ void spin_flag(int* flags, int idx, int target) {
    while (*((volatile int*)&flags[idx]) < target) __nanosleep(64);
}

// ---------------------------------------------------------------------------
// Prep kernels: fp32 -> fp16
// ---------------------------------------------------------------------------
__global__ void prep_cvt(const float* __restrict__ in, __half* __restrict__ out,
                         int total4)
{
    int i = blockIdx.x * 256 + threadIdx.x;
    if (i >= total4) return;
    float4 v = ((const float4*)in)[i];
    uint2 o;
    o.x = pack_h2(v.x, v.y);
    o.y = pack_h2(v.z, v.w);
    ((uint2*)out)[i] = o;
}

__global__ void transpose_nat(const float* __restrict__ in,
                              __half* __restrict__ out, int R, int C)
{
    __shared__ float t[32][33];
    int c0 = blockIdx.x * 32, r0 = blockIdx.y * 32;
    int x = threadIdx.x, y = threadIdx.y;
#pragma unroll
    for (int i = 0; i < 32; i += 8)
        t[y + i][x] = in[(size_t)(r0 + y + i) * C + c0 + x];
    __syncthreads();
#pragma unroll
    for (int i = 0; i < 32; i += 8)
        out[(size_t)(c0 + y + i) * R + r0 + x] = __float2half_rn(t[x][y + i]);
}

// ---------------------------------------------------------------------------
// GEMM tiling: CTA 128x128, K-block 64 (fp16), 3-stage cp.async, 2 CTAs/SM.
// smem row stride 72 halves (144 B) — conflict-free for frag loads.
// ---------------------------------------------------------------------------
#define GSTAGES 3
#define KB      64
#define HSTR    72
#define TILEH   (128*HSTR)              // halves per tile
#define TILE_B  (TILEH*2)               // bytes per tile (18432)
#define GEMM_SMEM (GSTAGES*2*TILE_B)    // 110592 B

#define AT_STR  72                      // attention smem stride (halves)
#define AT_BUF  (64*AT_STR*2)           // 9216 B per 64-row buffer

__device__ __forceinline__ void g_load_stage(uint32_t sbase, int s,
                                             const __half* Ag, const __half* Bg,
                                             int k0, int tid)
{
    uint32_t base = sbase + (uint32_t)s * 2 * TILE_B;
#pragma unroll
    for (int i = 0; i < 8; i++) {
        int f = tid + i * 128;          // 0..1023
        int row = f >> 3, c = f & 7;
        cp_async16(base + row * (HSTR * 2) + c * 16,
                   Ag + (size_t)row * CC + k0 + c * 8);
        cp_async16(base + TILE_B + row * (HSTR * 2) + c * 16,
                   Bg + (size_t)row * CC + k0 + c * 8);
    }
    asm volatile("cp.async.commit_group;" ::: "memory");
}

// Shared fp16 GEMM mainloop: acc[4][8][4] += A[128xK] * Bt[128xK]^T
__device__ __forceinline__ void gemm_mainloop(__half* smh, uint32_t sbase,
                                              const __half* Ag, const __half* Bg,
                                              int tid, int wm, int wn,
                                              int r, int l4,
                                              float acc[4][8][4])
{
    const int NIT = CC / KB;   // 16
#pragma unroll
    for (int s = 0; s < GSTAGES - 1; s++)
        g_load_stage(sbase, s, Ag, Bg, s * KB, tid);

    for (int it = 0; it < NIT; it++) {
        if (it < NIT - 1)
            asm volatile("cp.async.wait_group %0;" :: "n"(GSTAGES - 2) : "memory");
        else
            asm volatile("cp.async.wait_group 0;" ::: "memory");
        __syncthreads();

        if (it + GSTAGES - 1 < NIT)
            g_load_stage(sbase, (it + GSTAGES - 1) % GSTAGES, Ag, Bg,
                         (it + GSTAGES - 1) * KB, tid);

        const __half* As = smh + (size_t)(it % GSTAGES) * 2 * TILEH;
        const __half* Bs = As + TILEH;

#pragma unroll
        for (int h = 0; h < 4; h++) {           // 4 k16 chunks in KB=64
            const int kc = h * 16 + 2 * l4;
            uint32_t au[4][4];
#pragma unroll
            for (int mt = 0; mt < 4; mt++) {
                const __half* ap = As + (wm * 64 + mt * 16 + r) * HSTR + kc;
                au[mt][0] = *(const uint32_t*)ap;
                au[mt][1] = *(const uint32_t*)(ap + 8 * HSTR);
                au[mt][2] = *(const uint32_t*)(ap + 8);
                au[mt][3] = *(const uint32_t*)(ap + 8 * HSTR + 8);
            }
            uint32_t bu[8][2];
#pragma unroll
            for (int nt = 0; nt < 8; nt++) {
                const __half* bp = Bs + (wn * 64 + nt * 8 + r) * HSTR + kc;
                bu[nt][0] = *(const uint32_t*)bp;
                bu[nt][1] = *(const uint32_t*)(bp + 8);
            }
#pragma unroll
            for (int mt = 0; mt < 4; mt++)
#pragma unroll
                for (int nt = 0; nt < 8; nt++)
                    mma_f16(acc[mt][nt], au[mt][0], au[mt][1], au[mt][2],
                            au[mt][3], bu[nt][0], bu[nt][1]);
        }
    }
}

// ---------------------------------------------------------------------------
// Mega-kernel:
//   bids    0.. 767 : QKV GEMM (producers, release g_fq)
//   bids  768..1791 : flash attention (consume g_fq, release g_fy)
//   bids 1792..2047 : proj GEMM (consume g_fy)
// ---------------------------------------------------------------------------
__global__ __launch_bounds__(128, 2)
void mega_kernel(const __half* __restrict__ A, const __half* __restrict__ Bt,
                 const float* __restrict__ bias, __half* __restrict__ Yg,
                 const __half* __restrict__ Wp, const float* __restrict__ bp,
                 float* __restrict__ Out)
{
    extern __shared__ __align__(16) __half smh[];
    const uint32_t sbase = s2u(smh);
    const int tid = threadIdx.x;
    const int bid = blockIdx.x;
    const int lane = tid & 31;
    const int r    = lane >> 2;
    const int l4   = lane & 3;

    if (bid < 768) {
        // ================= QKV GEMM =================
        const int wid = tid >> 5;
        const int wm  = wid & 1;
        const int wn  = wid >> 1;
        const int rank = bid / 24, nblk = bid % 24;
        const int mblock = ((rank & 1) << 4) | (rank >> 1);   // batch-interleaved
        const int m0 = mblock << 7, n0 = nblk << 7;

        float acc[4][8][4];
#pragma unroll
        for (int mt = 0; mt < 4; mt++)
#pragma unroll
            for (int nt = 0; nt < 8; nt++)
#pragma unroll
                for (int j = 0; j < 4; j++) acc[mt][nt][j] = 0.0f;

        gemm_mainloop(smh, sbase, A + (size_t)m0 * CC, Bt + (size_t)n0 * CC,
                      tid, wm, wn, r, l4, acc);

        // Epilogue: bias + head scatter. q is pre-scaled by 0.125*log2e.
        const float QS = 0.125f * 1.44269504089f;
#pragma unroll
        for (int mt = 0; mt < 4; mt++) {
#pragma unroll
            for (int nt = 0; nt < 8; nt++) {
                const int row = m0 + wm * 64 + mt * 16 + r;
                const int c   = n0 + wn * 64 + nt * 8 + 2 * l4;
                const float b0v = __ldg(bias + c);
                const float b1v = __ldg(bias + c + 1);
                float v00 = acc[mt][nt][0] + b0v, v01 = acc[mt][nt][1] + b1v;
                float v10 = acc[mt][nt][2] + b0v, v11 = acc[mt][nt][3] + b1v;
                const int sec = c >> 10;
                const int cs = c & 1023, h = cs >> 6, d0 = cs & 63;
                const int b  = row >> 11;
                const int t0 = row & 2047;
                const int t1 = (row + 8) & 2047;
                if (sec == 2) {
                    __half* vb = g_v + ((size_t)(b * HH + h) * HD) * TT;
                    vb[(size_t)d0 * TT + t0]       = __float2half_rn(v00);
                    vb[(size_t)(d0 + 1) * TT + t0] = __float2half_rn(v01);
                    vb[(size_t)d0 * TT + t1]       = __float2half_rn(v10);
                    vb[(size_t)(d0 + 1) * TT + t1] = __float2half_rn(v11);
                } else {
                    if (sec == 0) { v00 *= QS; v01 *= QS; v10 *= QS; v11 *= QS; }
                    __half* basep = (sec == 0) ? g_q : g_k;
                    __half* p0 = basep + (((size_t)(b * HH + h) * TT + t0) * HD + d0);
                    __half* p1 = basep + (((size_t)(b * HH + h) * TT + t1) * HD + d0);
                    *(uint32_t*)p0 = pack_h2(v00, v01);
                    *(uint32_t*)p1 = pack_h2(v10, v11);
                }
            }
        }
        __syncthreads();
        __threadfence();
        if (tid == 0) atomicAdd(&g_fq[mblock], 1);
        return;
    }

    if (bid >= 1792) {
        // ================= Proj GEMM (consumes g_fy) =================
        const int pbid = bid - 1792;                // 0..255
        const int wid = tid >> 5;
        const int wm  = wid & 1;
        const int wn  = wid >> 1;
        const int rank = pbid >> 3, nblk = pbid & 7;
        const int mb_w = 15 - (rank >> 1);          // heavy-first
        const int b    = rank & 1;
        const int mblock = b * 16 + mb_w;
        const int m0 = mblock << 7, n0 = nblk << 7;

        if (tid == 0) {
            spin_flag(g_fy, mblock, 32);
            __threadfence();
        }
        __syncthreads();

        float acc[4][8][4];
#pragma unroll
        for (int mt = 0; mt < 4; mt++)
#pragma unroll
            for (int nt = 0; nt < 8; nt++)
#pragma unroll
                for (int j = 0; j < 4; j++) acc[mt][nt][j] = 0.0f;

        gemm_mainloop(smh, sbase, Yg + (size_t)m0 * CC, Wp + (size_t)n0 * CC,
                      tid, wm, wn, r, l4, acc);

#pragma unroll
        for (int mt = 0; mt < 4; mt++) {
#pragma unroll
            for (int nt = 0; nt < 8; nt++) {
                const int row = m0 + wm * 64 + mt * 16 + r;
                const int c   = n0 + wn * 64 + nt * 8 + 2 * l4;
                const float b0v = __ldg(bp + c);
                const float b1v = __ldg(bp + c + 1);
                *(float2*)(Out + (size_t)row * CC + c)
                    = make_float2(acc[mt][nt][0] + b0v, acc[mt][nt][1] + b1v);
                *(float2*)(Out + (size_t)(row + 8) * CC + c)
                    = make_float2(acc[mt][nt][2] + b0v, acc[mt][nt][3] + b1v);
            }
        }
        return;
    }

    // ================= Flash attention (q-tile 64, 4 warps, fp16 mma) =======
    {
        const int abid = bid - 768;
        const int qb   = 31 - (abid >> 5);          // heavy-first
        const int bh   = abid & 31;
        const int b    = bh >> 4, h = bh & 15;
        const int qbase = qb * 64;
        const int ntiles = qb + 1;
        const int bqoff  = b * 16;
        const int w = tid >> 5;

        // smem: Kb0,Kb1,Vb0,Vb1 (each 64 x AT_STR halves), then Ps (64 rows)
        __half* Kb0 = smh;
        __half* Kb1 = smh + 64 * AT_STR;
        __half* Vb0 = smh + 2 * 64 * AT_STR;
        __half* Vb1 = smh + 3 * 64 * AT_STR;
        __half* Ps  = smh + 4 * 64 * AT_STR;        // [64][72]
        const uint32_t koff = (uint32_t)AT_BUF;

        const __half* Qp  = g_q + (size_t)bh * TT * HD;
        const __half* Kp  = g_k + (size_t)bh * TT * HD;
        const __half* Vtp = g_v + (size_t)bh * HD * TT;

        if (tid == 0) {
            spin_flag(g_fq, bqoff + (qb >> 1), 24);
            spin_flag(g_fq, bqoff, 24);
            __threadfence();
        }
        __syncthreads();

        // Q (64x64 halves) into Ps; K/V tile 0 into buffers 0
#pragma unroll
        for (int i = 0; i < 4; i++) {
            int f = tid + i * 128;                  // 0..511
            int row = f >> 3, c = f & 7;
            cp_async16(sbase + (uint32_t)(4 * 64 * AT_STR + row * AT_STR) * 2 + c * 16,
                       Qp + (size_t)(qbase + row) * HD + c * 8);
            cp_async16(sbase + (uint32_t)(row * AT_STR) * 2 + c * 16,
                       Kp + (size_t)row * HD + c * 8);
            cp_async16(sbase + 2 * koff + (uint32_t)(row * AT_STR) * 2 + c * 16,
                       Vtp + (size_t)row * TT + c * 8);
        }
        asm volatile("cp.async.commit_group;" ::: "memory");
        asm volatile("cp.async.wait_group 0;" ::: "memory");
        __syncthreads();

        // Q fragments (pre-scaled at QKV epilogue): 4 chunks x 4 u32
        uint32_t aq[4][4];
        {
            const __half* q0 = Ps + (w * 16 + r) * AT_STR + 2 * l4;
#pragma unroll
            for (int hc = 0; hc < 4; hc++) {
                const __half* qp = q0 + hc * 16;
                aq[hc][0] = *(const uint32_t*)qp;
                aq[hc][1] = *(const uint32_t*)(qp + 8 * AT_STR);
                aq[hc][2] = *(const uint32_t*)(qp + 8);
                aq[hc][3] = *(const uint32_t*)(qp + 8 * AT_STR + 8);
            }
        }
        __syncthreads();   // Ps now free for P

        float O[8][4];
#pragma unroll
        for (int nt = 0; nt < 8; nt++)
#pragma unroll
            for (int j = 0; j < 4; j++) O[nt][j] = 0.0f;
        float m0v = -1e30f, m1v = -1e30f, l0v = 0.0f, l1v = 0.0f;

        const int tq0 = qbase + w * 16 + r;
        const int tq1 = tq0 + 8;
        __half* pw = Ps + (w * 16) * AT_STR;

        for (int kt = 0; kt < ntiles; kt++) {
            const int kbase = kt * 64;
            const int buf = kt & 1;
            const __half* Ksm = buf ? Kb1 : Kb0;
            const __half* VTs = buf ? Vb1 : Vb0;
            const bool more = (kt + 1 < ntiles);

            if (more) {
                const int nb = kbase + 64;
                uint32_t kd = sbase + (uint32_t)(buf ^ 1) * koff;
                uint32_t vd = sbase + 2 * koff + (uint32_t)(buf ^ 1) * koff;
#pragma unroll
                for (int i = 0; i < 4; i++) {
                    int f = tid + i * 128;
                    int row = f >> 3, c = f & 7;
                    cp_async16(kd + (uint32_t)(row * AT_STR) * 2 + c * 16,
                               Kp + (size_t)(nb + row) * HD + c * 8);
                    cp_async16(vd + (uint32_t)(row * AT_STR) * 2 + c * 16,
                               Vtp + (size_t)row * TT + nb + c * 8);
                }
                asm volatile("cp.async.commit_group;" ::: "memory");
            }

            // S = Q K^T (Q pre-scaled; log2-domain softmax)
            float s[8][4];
#pragma unroll
            for (int nt = 0; nt < 8; nt++) {
#pragma unroll
                for (int j = 0; j < 4; j++) s[nt][j] = 0.0f;
                const __half* kp = Ksm + (nt * 8 + r) * AT_STR + 2 * l4;
#pragma unroll
                for (int hc = 0; hc < 4; hc++) {
                    uint32_t b0 = *(const uint32_t*)(kp + hc * 16);
                    uint32_t b1 = *(const uint32_t*)(kp + hc * 16 + 8);
                    mma_f16(s[nt], aq[hc][0], aq[hc][1], aq[hc][2], aq[hc][3],
                            b0, b1);
                }
            }

            // causal mask (diagonal tile only)
            if (kbase + 63 > qbase + w * 16) {
#pragma unroll
                for (int nt = 0; nt < 8; nt++) {
                    int tk = kbase + nt * 8 + 2 * l4;
                    if (tk     > tq0) s[nt][0] = -1e30f;
                    if (tk + 1 > tq0) s[nt][1] = -1e30f;
                    if (tk     > tq1) s[nt][2] = -1e30f;
                    if (tk + 1 > tq1) s[nt][3] = -1e30f;
                }
            }

            // online softmax (log2 domain)
            float ml0 = -1e30f, ml1 = -1e30f;
#pragma unroll
            for (int nt = 0; nt < 8; nt++) {
                ml0 = fmaxf(ml0, fmaxf(s[nt][0], s[nt][1]));
                ml1 = fmaxf(ml1, fmaxf(s[nt][2], s[nt][3]));
            }
            ml0 = fmaxf(ml0, __shfl_xor_sync(0xffffffffu, ml0, 1));
            ml0 = fmaxf(ml0, __shfl_xor_sync(0xffffffffu, ml0, 2));
            ml1 = fmaxf(ml1, __shfl_xor_sync(0xffffffffu, ml1, 1));
            ml1 = fmaxf(ml1, __shfl_xor_sync(0xffffffffu, ml1, 2));
            float mn0 = fmaxf(m0v, ml0), mn1 = fmaxf(m1v, ml1);
            float c0 = ex2(m0v - mn0), c1 = ex2(m1v - mn1);
            float ps0 = 0.0f, ps1 = 0.0f;
#pragma unroll
            for (int nt = 0; nt < 8; nt++) {
                s[nt][0] = ex2(s[nt][0] - mn0); ps0 += s[nt][0];
                s[nt][1] = ex2(s[nt][1] - mn0); ps0 += s[nt][1];
                s[nt][2] = ex2(s[nt][2] - mn1); ps1 += s[nt][2];
                s[nt][3] = ex2(s[nt][3] - mn1); ps1 += s[nt][3];
            }
            ps0 += __shfl_xor_sync(0xffffffffu, ps0, 1);
            ps0 += __shfl_xor_sync(0xffffffffu, ps0, 2);
            ps1 += __shfl_xor_sync(0xffffffffu, ps1, 1);
            ps1 += __shfl_xor_sync(0xffffffffu, ps1, 2);
            l0v = l0v * c0 + ps0; m0v = mn0;
            l1v = l1v * c1 + ps1; m1v = mn1;
#pragma unroll
            for (int nt = 0; nt < 8; nt++) {
                O[nt][0] *= c0; O[nt][1] *= c0;
                O[nt][2] *= c1; O[nt][3] *= c1;
            }

            // P -> per-warp smem as half2
#pragma unroll
            for (int nt = 0; nt < 8; nt++) {
                *(uint32_t*)(pw + r * AT_STR + nt * 8 + 2 * l4)
                    = pack_h2(s[nt][0], s[nt][1]);
                *(uint32_t*)(pw + (r + 8) * AT_STR + nt * 8 + 2 * l4)
                    = pack_h2(s[nt][2], s[nt][3]);
            }
            __syncwarp();

            // P fragments
            uint32_t pa[4][4];
            {
                const __half* p0 = pw + r * AT_STR + 2 * l4;
#pragma unroll
                for (int hc = 0; hc < 4; hc++) {
                    const __half* pp = p0 + hc * 16;
                    pa[hc][0] = *(const uint32_t*)pp;
                    pa[hc][1] = *(const uint32_t*)(pp + 8 * AT_STR);
                    pa[hc][2] = *(const uint32_t*)(pp + 8);
                    pa[hc][3] = *(const uint32_t*)(pp + 8 * AT_STR + 8);
                }
            }

            // O += P V
#pragma unroll
            for (int nt = 0; nt < 8; nt++) {
                const __half* vp = VTs + (nt * 8 + r) * AT_STR + 2 * l4;
#pragma unroll
                for (int hc = 0; hc < 4; hc++) {
                    uint32_t b0 = *(const uint32_t*)(vp + hc * 16);
                    uint32_t b1 = *(const uint32_t*)(vp + hc * 16 + 8);
                    mma_f16(O[nt], pa[hc][0], pa[hc][1], pa[hc][2], pa[hc][3],
                            b0, b1);
                }
            }

            if (more) {
                asm volatile("cp.async.wait_group 0;" ::: "memory");
                if (tid == 0) {
                    if (kt + 2 < ntiles) spin_flag(g_fq, bqoff + ((kt + 2) >> 1), 24);
                    __threadfence();
                }
                __syncthreads();
            }
        }

        // Epilogue: normalize, half y, release g_fy
        const int hb = h * 64;
        const float inv0 = 1.0f / l0v, inv1 = 1.0f / l1v;
        __half* y0 = Yg + (size_t)(b * TT + tq0) * CC;
        __half* y1 = Yg + (size_t)(b * TT + tq1) * CC;
#pragma unroll
        for (int nt = 0; nt < 8; nt++) {
            int c = hb + nt * 8 + 2 * l4;
            *(uint32_t*)(y0 + c) = pack_h2(O[nt][0] * inv0, O[nt][1] * inv0);
            *(uint32_t*)(y1 + c) = pack_h2(O[nt][2] * inv1, O[nt][3] * inv1);
        }
        __syncthreads();
        __threadfence();
        if (tid == 0) atomicAdd(&g_fy[b * 16 + (qb >> 1)], 1);
    }
}

// ---------------------------------------------------------------------------
// Launch
// ---------------------------------------------------------------------------
extern "C" void kernel_launch(void* const* d_in, const int* in_sizes, int n_in,
                              void* d_out, int out_size)
{
    const float* x     = (const float*)d_in[0];
    const float* Wqkv  = (const float*)d_in[1];
    const float* bqkv  = (const float*)d_in[2];
    const float* Wproj = (const float*)d_in[3];
    const float* bproj = (const float*)d_in[4];
    float* out = (float*)d_out;
    (void)in_sizes; (void)n_in; (void)out_size;

    __half *yp, *xp, *wtq, *wtp;
    int *fq, *fy;
    cudaGetSymbolAddress((void**)&yp,  g_y);
    cudaGetSymbolAddress((void**)&xp,  g_xp);
    cudaGetSymbolAddress((void**)&wtq, g_wtq);
    cudaGetSymbolAddress((void**)&wtp, g_wtp);
    cudaGetSymbolAddress((void**)&fq,  g_fq);
    cudaGetSymbolAddress((void**)&fy,  g_fy);

    cudaFuncSetAttribute(mega_kernel, cudaFuncAttributeMaxDynamicSharedMemorySize, GEMM_SMEM);

    cudaMemsetAsync(fq, 0, 32 * sizeof(int));
    cudaMemsetAsync(fy, 0, 32 * sizeof(int));

    {
        int total4 = MROWS * CC / 4;
        prep_cvt<<<(total4 + 255) / 256, 256>>>(x, xp, total4);
        transpose_nat<<<dim3(N_QKV / 32, CC / 32), dim3(32, 8)>>>(Wqkv, wtq, CC, N_QKV);
        transpose_nat<<<dim3(CC / 32, CC / 32), dim3(32, 8)>>>(Wproj, wtp, CC, CC);
    }

    // Fully fused: QKV GEMM -> attention -> proj GEMM via device-side flags
    mega_kernel<<<768 + 1024 + 256, 128, GEMM_SMEM>>>(xp, wtq, bqkv, yp,
                                                      wtp, bproj, out);
}

// round 12
// speedup vs baseline: 2.3410x; 1.0503x over previous
#include <cuda_runtime.h>
#include <cuda_fp16.h>
#include <math.h>
#include <stdint.h>

#define BB   2
#define TT   2048
#define CC   1024
#define HH   16
#define HD   64
#define MROWS (BB*TT)        // 4096
#define N_QKV (3*CC)         // 3072

// ---------------------------------------------------------------------------
// Scratch (device globals) — fp16
// ---------------------------------------------------------------------------
__device__ __align__(1024) __half g_q[BB*HH*TT*HD];   // [B,H,T,HD], pre-scaled by 0.125*log2e
__device__ __align__(1024) __half g_k[BB*HH*TT*HD];   // [B,H,T,HD]
__device__ __align__(1024) __half g_v[BB*HH*TT*HD];   // [B,H,HD,T]  (TRANSPOSED)
__device__ __align__(1024) __half g_y[MROWS*CC];      // attn out
__device__ __align__(1024) __half g_xp[MROWS*CC];     // x
__device__ __align__(1024) __half g_wtq[N_QKV*CC];    // Wqkv^T
__device__ __align__(1024) __half g_wtp[CC*CC];       // Wproj^T
__device__ int g_fq[32];                              // per-m-block QKV flags
__device__ int g_fy[32];                              // per-m-block attn-out flags

// ---------------------------------------------------------------------------
// Helpers
// ---------------------------------------------------------------------------
__device__ __forceinline__ float ex2(float x) {
    float r;
    asm("ex2.approx.f32 %0, %1;" : "=f"(r) : "f"(x));
    return r;
}

__device__ __forceinline__ uint32_t pack_h2(float lo, float hi) {
    uint32_t r;
    asm("cvt.rn.f16x2.f32 %0, %1, %2;" : "=r"(r) : "f"(hi), "f"(lo));
    return r;
}

__device__ __forceinline__ uint32_t s2u(const void* p) {
    uint32_t a;
    asm("{ .reg .u64 t; cvta.to.shared.u64 t, %1; cvt.u32.u64 %0, t; }"
        : "=r"(a) : "l"(p));
    return a;
}

__device__ __forceinline__ void cp_async16(uint32_t dst, const void* src) {
    asm volatile("cp.async.cg.shared.global [%0], [%1], 16;"
                 :: "r"(dst), "l"(src) : "memory");
}

// ldmatrix x4: four 8x8 f16 matrices; lane groups 0-7/8-15/16-23/24-31 supply
// the row addresses of matrices 0..3 respectively.
__device__ __forceinline__ void ldsm4(uint32_t r[4], uint32_t addr) {
    asm volatile("ldmatrix.sync.aligned.m8n8.x4.shared.b16 {%0,%1,%2,%3}, [%4];"
                 : "=r"(r[0]), "=r"(r[1]), "=r"(r[2]), "=r"(r[3]) : "r"(addr));
}

// fp16 mma: D(16x8,f32) += A(16x16,f16) * B(16x8,f16)  [row.col]
__device__ __forceinline__ void mma_f16(float d[4], uint32_t a0, uint32_t a1,
                                        uint32_t a2, uint32_t a3,
                                        uint32_t b0, uint32_t b1)
{
    asm volatile(
        "mma.sync.aligned.m16n8k16.row.col.f32.f16.f16.f32 "
        "{%0,%1,%2,%3}, {%4,%5,%6,%7}, {%8,%9}, {%0,%1,%2,%3};"
        : "+f"(d[0]), "+f"(d[1]), "+f"(d[2]), "+f"(d[3])
        : "r"(a0), "r"(a1), "r"(a2), "r"(a3), "r"(b0), "r"(b1));
}

__device__ __forceinline__ void spin_flag(int* flags, int idx, int target) {
    while (*((volatile int*)&flags[idx]) < target) __nanosleep(64);
}

// ---------------------------------------------------------------------------
// Combined prep kernel (one launch): x cvt + both weight transposes + flag zero
//   bids 0..4095          : x fp32 -> fp16 (float4 granules)
//   bids 4096..7167       : Wqkv transpose (96 x 32 tiles)
//   bids 7168..8191       : Wproj transpose (32 x 32 tiles)
// ---------------------------------------------------------------------------
__global__ void prep_all(const float* __restrict__ x,
                         const float* __restrict__ Wqkv,
                         const float* __restrict__ Wproj,
                         __half* __restrict__ xp,
                         __half* __restrict__ wtq,
                         __half* __restrict__ wtp)
{
    const int bid = blockIdx.x;
    const int tid = threadIdx.x;
    if (bid == 0 && tid < 64) {
        if (tid < 32) g_fq[tid] = 0;
        else          g_fy[tid - 32] = 0;
    }
    if (bid < 4096) {
        int i = bid * 256 + tid;
        float4 v = ((const float4*)x)[i];
        uint2 o;
        o.x = pack_h2(v.x, v.y);
        o.y = pack_h2(v.z, v.w);
        ((uint2*)xp)[i] = o;
        return;
    }
    __shared__ float t[32][33];
    const float* in;
    __half* out;
    int R, C, bx, by;
    if (bid < 4096 + 3072) {
        int tb = bid - 4096;
        in = Wqkv; out = wtq; R = CC; C = N_QKV;
        bx = tb % 96; by = tb / 96;
    } else {
        int tb = bid - 4096 - 3072;
        in = Wproj; out = wtp; R = CC; C = CC;
        bx = tb & 31; by = tb >> 5;
    }
    int xx = tid & 31, yy = tid >> 5;     // 32 x 8
    int c0 = bx * 32, r0 = by * 32;
#pragma unroll
    for (int i = 0; i < 32; i += 8)
        t[yy + i][xx] = in[(size_t)(r0 + yy + i) * C + c0 + xx];
    __syncthreads();
#pragma unroll
    for (int i = 0; i < 32; i += 8)
        out[(size_t)(c0 + yy + i) * R + r0 + xx] = __float2half_rn(t[xx][yy + i]);
}

// ---------------------------------------------------------------------------
// GEMM tiling: CTA 128x128, K-block 64 (fp16), 3-stage cp.async, 2 CTAs/SM.
// smem row stride 72 halves (144 B) — conflict-free LDSM.
// ---------------------------------------------------------------------------
#define GSTAGES 3
#define KB      64
#define HSTR    72
#define TILEH   (128*HSTR)              // halves per tile
#define TILE_B  (TILEH*2)               // bytes per tile (18432)
#define GEMM_SMEM (GSTAGES*2*TILE_B)    // 110592 B

#define AT_STR  72                      // attention smem stride (halves)
#define AT_BUF  (64*AT_STR*2)           // bytes per 64-row buffer

__device__ __forceinline__ void g_load_stage(uint32_t sbase, int s,
                                             const __half* Ag, const __half* Bg,
                                             int k0, int tid)
{
    uint32_t base = sbase + (uint32_t)s * 2 * TILE_B;
#pragma unroll
    for (int i = 0; i < 8; i++) {
        int f = tid + i * 128;          // 0..1023
        int row = f >> 3, c = f & 7;
        cp_async16(base + row * (HSTR * 2) + c * 16,
                   Ag + (size_t)row * CC + k0 + c * 8);
        cp_async16(base + TILE_B + row * (HSTR * 2) + c * 16,
                   Bg + (size_t)row * CC + k0 + c * 8);
    }
    asm volatile("cp.async.commit_group;" ::: "memory");
}

// Shared fp16 GEMM mainloop (ldmatrix fragments): acc += A[128xK] * Bt[128xK]^T
__device__ __forceinline__ void gemm_mainloop(uint32_t sbase,
                                              const __half* Ag, const __half* Bg,
                                              int tid, int wm, int wn, int lane,
                                              float acc[4][8][4])
{
    // A-type lane geometry (16x16 fragments)
    const int aRow = wm * 64 + (lane & 15);
    const int aCol = ((lane >> 4) & 1) * 8;
    // B-type lane geometry (16-row pair of 16x8 fragments)
    const int bRow = wn * 64 + ((lane >> 4) << 3) + (lane & 7);
    const int bCol = ((lane >> 3) & 1) * 8;

    const int NIT = CC / KB;   // 16
#pragma unroll
    for (int s = 0; s < GSTAGES - 1; s++)
        g_load_stage(sbase, s, Ag, Bg, s * KB, tid);

    for (int it = 0; it < NIT; it++) {
        if (it < NIT - 1)
            asm volatile("cp.async.wait_group %0;" :: "n"(GSTAGES - 2) : "memory");
        else
            asm volatile("cp.async.wait_group 0;" ::: "memory");
        __syncthreads();

        if (it + GSTAGES - 1 < NIT)
            g_load_stage(sbase, (it + GSTAGES - 1) % GSTAGES, Ag, Bg,
                         (it + GSTAGES - 1) * KB, tid);

        const uint32_t Aab = sbase + (uint32_t)(it % GSTAGES) * 2 * TILE_B;
        const uint32_t Bab = Aab + TILE_B;

#pragma unroll
        for (int h = 0; h < 4; h++) {           // 4 k16 chunks in KB=64
            uint32_t au[4][4];
#pragma unroll
            for (int mt = 0; mt < 4; mt++)
                ldsm4(au[mt], Aab + (uint32_t)(((aRow + mt * 16) * HSTR
                                                + h * 16 + aCol) * 2));
            uint32_t bu[4][4];
#pragma unroll
            for (int p = 0; p < 4; p++)
                ldsm4(bu[p], Bab + (uint32_t)(((bRow + p * 16) * HSTR
                                               + h * 16 + bCol) * 2));
#pragma unroll
            for (int mt = 0; mt < 4; mt++)
#pragma unroll
                for (int nt = 0; nt < 8; nt++)
                    mma_f16(acc[mt][nt], au[mt][0], au[mt][1], au[mt][2],
                            au[mt][3], bu[nt >> 1][(nt & 1) * 2],
                            bu[nt >> 1][(nt & 1) * 2 + 1]);
        }
    }
}

// ---------------------------------------------------------------------------
// Mega-kernel:
//   bids    0.. 767 : QKV GEMM (producers, release g_fq)
//   bids  768..1791 : flash attention (consume g_fq, release g_fy)
//   bids 1792..2047 : proj GEMM (consume g_fy)
// ---------------------------------------------------------------------------
__global__ __launch_bounds__(128, 2)
void mega_kernel(const __half* __restrict__ A, const __half* __restrict__ Bt,
                 const float* __restrict__ bias, __half* __restrict__ Yg,
                 const __half* __restrict__ Wp, const float* __restrict__ bp,
                 float* __restrict__ Out)
{
    extern __shared__ __align__(16) __half smh[];
    const uint32_t sbase = s2u(smh);
    const int tid = threadIdx.x;
    const int bid = blockIdx.x;
    const int lane = tid & 31;
    const int r    = lane >> 2;
    const int l4   = lane & 3;

    if (bid < 768) {
        // ================= QKV GEMM =================
        const int wid = tid >> 5;
        const int wm  = wid & 1;
        const int wn  = wid >> 1;
        const int rank = bid / 24, nblk = bid % 24;
        const int mblock = ((rank & 1) << 4) | (rank >> 1);   // batch-interleaved
        const int m0 = mblock << 7, n0 = nblk << 7;

        float acc[4][8][4];
#pragma unroll
        for (int mt = 0; mt < 4; mt++)
#pragma unroll
            for (int nt = 0; nt < 8; nt++)
#pragma unroll
                for (int j = 0; j < 4; j++) acc[mt][nt][j] = 0.0f;

        gemm_mainloop(sbase, A + (size_t)m0 * CC, Bt + (size_t)n0 * CC,
                      tid, wm, wn, lane, acc);

        // Epilogue: bias + head scatter. q is pre-scaled by 0.125*log2e.
        const float QS = 0.125f * 1.44269504089f;
#pragma unroll
        for (int mt = 0; mt < 4; mt++) {
#pragma unroll
            for (int nt = 0; nt < 8; nt++) {
                const int row = m0 + wm * 64 + mt * 16 + r;
                const int c   = n0 + wn * 64 + nt * 8 + 2 * l4;
                const float b0v = __ldg(bias + c);
                const float b1v = __ldg(bias + c + 1);
                float v00 = acc[mt][nt][0] + b0v, v01 = acc[mt][nt][1] + b1v;
                float v10 = acc[mt][nt][2] + b0v, v11 = acc[mt][nt][3] + b1v;
                const int sec = c >> 10;
                const int cs = c & 1023, h = cs >> 6, d0 = cs & 63;
                const int b  = row >> 11;
                const int t0 = row & 2047;
                const int t1 = (row + 8) & 2047;
                if (sec == 2) {
                    __half* vb = g_v + ((size_t)(b * HH + h) * HD) * TT;
                    vb[(size_t)d0 * TT + t0]       = __float2half_rn(v00);
                    vb[(size_t)(d0 + 1) * TT + t0] = __float2half_rn(v01);
                    vb[(size_t)d0 * TT + t1]       = __float2half_rn(v10);
                    vb[(size_t)(d0 + 1) * TT + t1] = __float2half_rn(v11);
                } else {
                    if (sec == 0) { v00 *= QS; v01 *= QS; v10 *= QS; v11 *= QS; }
                    __half* basep = (sec == 0) ? g_q : g_k;
                    __half* p0 = basep + (((size_t)(b * HH + h) * TT + t0) * HD + d0);
                    __half* p1 = basep + (((size_t)(b * HH + h) * TT + t1) * HD + d0);
                    *(uint32_t*)p0 = pack_h2(v00, v01);
                    *(uint32_t*)p1 = pack_h2(v10, v11);
                }
            }
        }
        __syncthreads();
        __threadfence();
        if (tid == 0) atomicAdd(&g_fq[mblock], 1);
        return;
    }

    if (bid >= 1792) {
        // ================= Proj GEMM (consumes g_fy) =================
        const int pbid = bid - 1792;                // 0..255
        const int wid = tid >> 5;
        const int wm  = wid & 1;
        const int wn  = wid >> 1;
        const int rank = pbid >> 3, nblk = pbid & 7;
        const int mb_w = 15 - (rank >> 1);          // heavy-first
        const int b    = rank & 1;
        const int mblock = b * 16 + mb_w;
        const int m0 = mblock << 7, n0 = nblk << 7;

        if (tid == 0) {
            spin_flag(g_fy, mblock, 32);
            __threadfence();
        }
        __syncthreads();

        float acc[4][8][4];
#pragma unroll
        for (int mt = 0; mt < 4; mt++)
#pragma unroll
            for (int nt = 0; nt < 8; nt++)
#pragma unroll
                for (int j = 0; j < 4; j++) acc[mt][nt][j] = 0.0f;

        gemm_mainloop(sbase, Yg + (size_t)m0 * CC, Wp + (size_t)n0 * CC,
                      tid, wm, wn, lane, acc);

#pragma unroll
        for (int mt = 0; mt < 4; mt++) {
#pragma unroll
            for (int nt = 0; nt < 8; nt++) {
                const int row = m0 + wm * 64 + mt * 16 + r;
                const int c   = n0 + wn * 64 + nt * 8 + 2 * l4;
                const float b0v = __ldg(bp + c);
                const float b1v = __ldg(bp + c + 1);
                *(float2*)(Out + (size_t)row * CC + c)
                    = make_float2(acc[mt][nt][0] + b0v, acc[mt][nt][1] + b1v);
                *(float2*)(Out + (size_t)(row + 8) * CC + c)
                    = make_float2(acc[mt][nt][2] + b0v, acc[mt][nt][3] + b1v);
            }
        }
        return;
    }

    // ================= Flash attention (q-tile 64, 4 warps, fp16 mma) =======
    {
        const int abid = bid - 768;
        const int qb   = 31 - (abid >> 5);          // heavy-first
        const int bh   = abid & 31;
        const int b    = bh >> 4, h = bh & 15;
        const int qbase = qb * 64;
        const int ntiles = qb + 1;
        const int bqoff  = b * 16;
        const int w = tid >> 5;

        const uint32_t koff = (uint32_t)AT_BUF;
        const uint32_t PS_B = (uint32_t)(4 * 64 * AT_STR * 2);   // Ps byte offset

        const __half* Qp  = g_q + (size_t)bh * TT * HD;
        const __half* Kp  = g_k + (size_t)bh * TT * HD;
        const __half* Vtp = g_v + (size_t)bh * HD * TT;

        if (tid == 0) {
            spin_flag(g_fq, bqoff + (qb >> 1), 24);
            spin_flag(g_fq, bqoff, 24);
            __threadfence();
        }
        __syncthreads();

        // Q (64x64 halves) into Ps; K/V tile 0 into buffers 0
#pragma unroll
        for (int i = 0; i < 4; i++) {
            int f = tid + i * 128;                  // 0..511
            int row = f >> 3, c = f & 7;
            cp_async16(sbase + PS_B + (uint32_t)(row * AT_STR) * 2 + c * 16,
                       Qp + (size_t)(qbase + row) * HD + c * 8);
            cp_async16(sbase + (uint32_t)(row * AT_STR) * 2 + c * 16,
                       Kp + (size_t)row * HD + c * 8);
            cp_async16(sbase + 2 * koff + (uint32_t)(row * AT_STR) * 2 + c * 16,
                       Vtp + (size_t)row * TT + c * 8);
        }
        asm volatile("cp.async.commit_group;" ::: "memory");
        asm volatile("cp.async.wait_group 0;" ::: "memory");
        __syncthreads();

        // Fragment lane geometry
        const int aRowL = lane & 15;                 // A-type (Q / P)
        const int aColL = ((lane >> 4) & 1) * 8;
        const int bRowL = ((lane >> 4) << 3) + (lane & 7);   // B-type (K / V)
        const int bColL = ((lane >> 3) & 1) * 8;

        // Q fragments (pre-scaled at QKV epilogue): 4 chunks via ldmatrix
        uint32_t aq[4][4];
#pragma unroll
        for (int hc = 0; hc < 4; hc++)
            ldsm4(aq[hc], sbase + PS_B +
                  (uint32_t)(((w * 16 + aRowL) * AT_STR + hc * 16 + aColL) * 2));
        __syncthreads();   // Ps now free for P

        float O[8][4];
#pragma unroll
        for (int nt = 0; nt < 8; nt++)
#pragma unroll
            for (int j = 0; j < 4; j++) O[nt][j] = 0.0f;
        float m0v = -1e30f, m1v = -1e30f, l0v = 0.0f, l1v = 0.0f;

        const int tq0 = qbase + w * 16 + r;
        const int tq1 = tq0 + 8;
        __half* pw = smh + 4 * 64 * AT_STR + (w * 16) * AT_STR;
        const uint32_t pwAddr = sbase + PS_B + (uint32_t)(w * 16 * AT_STR * 2);

        for (int kt = 0; kt < ntiles; kt++) {
            const int kbase = kt * 64;
            const int buf = kt & 1;
            const uint32_t kAddr = sbase + (uint32_t)buf * koff;
            const uint32_t vAddr = sbase + 2 * koff + (uint32_t)buf * koff;
            const bool more = (kt + 1 < ntiles);

            if (more) {
                const int nb = kbase + 64;
                uint32_t kd = sbase + (uint32_t)(buf ^ 1) * koff;
                uint32_t vd = sbase + 2 * koff + (uint32_t)(buf ^ 1) * koff;
#pragma unroll
                for (int i = 0; i < 4; i++) {
                    int f = tid + i * 128;
                    int row = f >> 3, c = f & 7;
                    cp_async16(kd + (uint32_t)(row * AT_STR) * 2 + c * 16,
                               Kp + (size_t)(nb + row) * HD + c * 8);
                    cp_async16(vd + (uint32_t)(row * AT_STR) * 2 + c * 16,
                               Vtp + (size_t)row * TT + nb + c * 8);
                }
                asm volatile("cp.async.commit_group;" ::: "memory");
            }

            // S = Q K^T (Q pre-scaled; log2-domain softmax)
            float s[8][4];
#pragma unroll
            for (int nt = 0; nt < 8; nt++)
#pragma unroll
                for (int j = 0; j < 4; j++) s[nt][j] = 0.0f;
#pragma unroll
            for (int hc = 0; hc < 4; hc++) {
                uint32_t ku[4][4];
#pragma unroll
                for (int p = 0; p < 4; p++)
                    ldsm4(ku[p], kAddr + (uint32_t)(((p * 16 + bRowL) * AT_STR
                                                    + hc * 16 + bColL) * 2));
#pragma unroll
                for (int nt = 0; nt < 8; nt++)
                    mma_f16(s[nt], aq[hc][0], aq[hc][1], aq[hc][2], aq[hc][3],
                            ku[nt >> 1][(nt & 1) * 2],
                            ku[nt >> 1][(nt & 1) * 2 + 1]);
            }

            // causal mask (diagonal tile only)
            if (kbase + 63 > qbase + w * 16) {
#pragma unroll
                for (int nt = 0; nt < 8; nt++) {
                    int tk = kbase + nt * 8 + 2 * l4;
                    if (tk     > tq0) s[nt][0] = -1e30f;
                    if (tk + 1 > tq0) s[nt][1] = -1e30f;
                    if (tk     > tq1) s[nt][2] = -1e30f;
                    if (tk + 1 > tq1) s[nt][3] = -1e30f;
                }
            }

            // online softmax (log2 domain)
            float ml0 = -1e30f, ml1 = -1e30f;
#pragma unroll
            for (int nt = 0; nt < 8; nt++) {
                ml0 = fmaxf(ml0, fmaxf(s[nt][0], s[nt][1]));
                ml1 = fmaxf(ml1, fmaxf(s[nt][2], s[nt][3]));
            }
            ml0 = fmaxf(ml0, __shfl_xor_sync(0xffffffffu, ml0, 1));
            ml0 = fmaxf(ml0, __shfl_xor_sync(0xffffffffu, ml0, 2));
            ml1 = fmaxf(ml1, __shfl_xor_sync(0xffffffffu, ml1, 1));
            ml1 = fmaxf(ml1, __shfl_xor_sync(0xffffffffu, ml1, 2));
            float mn0 = fmaxf(m0v, ml0), mn1 = fmaxf(m1v, ml1);
            float c0 = ex2(m0v - mn0), c1 = ex2(m1v - mn1);
            float ps0 = 0.0f, ps1 = 0.0f;
#pragma unroll
            for (int nt = 0; nt < 8; nt++) {
                s[nt][0] = ex2(s[nt][0] - mn0); ps0 += s[nt][0];
                s[nt][1] = ex2(s[nt][1] - mn0); ps0 += s[nt][1];
                s[nt][2] = ex2(s[nt][2] - mn1); ps1 += s[nt][2];
                s[nt][3] = ex2(s[nt][3] - mn1); ps1 += s[nt][3];
            }
            ps0 += __shfl_xor_sync(0xffffffffu, ps0, 1);
            ps0 += __shfl_xor_sync(0xffffffffu, ps0, 2);
            ps1 += __shfl_xor_sync(0xffffffffu, ps1, 1);
            ps1 += __shfl_xor_sync(0xffffffffu, ps1, 2);
            l0v = l0v * c0 + ps0; m0v = mn0;
            l1v = l1v * c1 + ps1; m1v = mn1;
#pragma unroll
            for (int nt = 0; nt < 8; nt++) {
                O[nt][0] *= c0; O[nt][1] *= c0;
                O[nt][2] *= c1; O[nt][3] *= c1;
            }

            // P -> per-warp smem as half2
#pragma unroll
            for (int nt = 0; nt < 8; nt++) {
                *(uint32_t*)(pw + r * AT_STR + nt * 8 + 2 * l4)
                    = pack_h2(s[nt][0], s[nt][1]);
                *(uint32_t*)(pw + (r + 8) * AT_STR + nt * 8 + 2 * l4)
                    = pack_h2(s[nt][2], s[nt][3]);
            }
            __syncwarp();

            // O += P V (ldmatrix fragments)
#pragma unroll
            for (int hc = 0; hc < 4; hc++) {
                uint32_t pa[4];
                ldsm4(pa, pwAddr + (uint32_t)((aRowL * AT_STR
                                               + hc * 16 + aColL) * 2));
                uint32_t vu[4][4];
#pragma unroll
                for (int p = 0; p < 4; p++)
                    ldsm4(vu[p], vAddr + (uint32_t)(((p * 16 + bRowL) * AT_STR
                                                    + hc * 16 + bColL) * 2));
#pragma unroll
                for (int nt = 0; nt < 8; nt++)
                    mma_f16(O[nt], pa[0], pa[1], pa[2], pa[3],
                            vu[nt >> 1][(nt & 1) * 2],
                            vu[nt >> 1][(nt & 1) * 2 + 1]);
            }

            if (more) {
                asm volatile("cp.async.wait_group 0;" ::: "memory");
                if (tid == 0) {
                    if (kt + 2 < ntiles) spin_flag(g_fq, bqoff + ((kt + 2) >> 1), 24);
                    __threadfence();
                }
                __syncthreads();
            }
        }

        // Epilogue: normalize, half y, release g_fy
        const int hb = h * 64;
        const float inv0 = 1.0f / l0v, inv1 = 1.0f / l1v;
        __half* y0 = Yg + (size_t)(b * TT + tq0) * CC;
        __half* y1 = Yg + (size_t)(b * TT + tq1) * CC;
#pragma unroll
        for (int nt = 0; nt < 8; nt++) {
            int c = hb + nt * 8 + 2 * l4;
            *(uint32_t*)(y0 + c) = pack_h2(O[nt][0] * inv0, O[nt][1] * inv0);
            *(uint32_t*)(y1 + c) = pack_h2(O[nt][2] * inv1, O[nt][3] * inv1);
        }
        __syncthreads();
        __threadfence();
        if (tid == 0) atomicAdd(&g_fy[b * 16 + (qb >> 1)], 1);
    }
}

// ---------------------------------------------------------------------------
// Launch
// ---------------------------------------------------------------------------
extern "C" void kernel_launch(void* const* d_in, const int* in_sizes, int n_in,
                              void* d_out, int out_size)
{
    const float* x     = (const float*)d_in[0];
    const float* Wqkv  = (const float*)d_in[1];
    const float* bqkv  = (const float*)d_in[2];
    const float* Wproj = (const float*)d_in[3];
    const float* bproj = (const float*)d_in[4];
    float* out = (float*)d_out;
    (void)in_sizes; (void)n_in; (void)out_size;

    __half *yp, *xp, *wtq, *wtp;
    cudaGetSymbolAddress((void**)&yp,  g_y);
    cudaGetSymbolAddress((void**)&xp,  g_xp);
    cudaGetSymbolAddress((void**)&wtq, g_wtq);
    cudaGetSymbolAddress((void**)&wtp, g_wtp);

    cudaFuncSetAttribute(mega_kernel, cudaFuncAttributeMaxDynamicSharedMemorySize, GEMM_SMEM);

    // One prep launch: x cvt + weight transposes + flag zeroing
    prep_all<<<4096 + 3072 + 1024, 256>>>(x, Wqkv, Wproj, xp, wtq, wtp);

    // Fully fused: QKV GEMM -> attention -> proj GEMM via device-side flags
    mega_kernel<<<768 + 1024 + 256, 128, GEMM_SMEM>>>(xp, wtq, bqkv, yp,
                                                      wtp, bproj, out);
}

// round 13
// speedup vs baseline: 2.4282x; 1.0372x over previous
#include <cuda_runtime.h>
#include <cuda_fp16.h>
#include <math.h>
#include <stdint.h>

#define BB   2
#define TT   2048
#define CC   1024
#define HH   16
#define HD   64
#define MROWS (BB*TT)        // 4096
#define N_QKV (3*CC)         // 3072

// ---------------------------------------------------------------------------
// Scratch (device globals) — fp16
// ---------------------------------------------------------------------------
__device__ __align__(1024) __half g_q[BB*HH*TT*HD];   // [B,H,T,HD], pre-scaled by 0.125*log2e
__device__ __align__(1024) __half g_k[BB*HH*TT*HD];   // [B,H,T,HD]
__device__ __align__(1024) __half g_v[BB*HH*TT*HD];   // [B,H,HD,T]  (TRANSPOSED)
__device__ __align__(1024) __half g_y[MROWS*CC];      // attn out
__device__ __align__(1024) __half g_xp[MROWS*CC];     // x
__device__ __align__(1024) __half g_wtq[N_QKV*CC];    // Wqkv^T
__device__ __align__(1024) __half g_wtp[CC*CC];       // Wproj^T
__device__ int g_fq[32];                              // per-m-block QKV flags
__device__ int g_fy[32];                              // per-m-block attn-out flags

// ---------------------------------------------------------------------------
// Helpers
// ---------------------------------------------------------------------------
__device__ __forceinline__ float ex2(float x) {
    float r;
    asm("ex2.approx.f32 %0, %1;" : "=f"(r) : "f"(x));
    return r;
}

__device__ __forceinline__ uint32_t pack_h2(float lo, float hi) {
    uint32_t r;
    asm("cvt.rn.f16x2.f32 %0, %1, %2;" : "=r"(r) : "f"(hi), "f"(lo));
    return r;
}

__device__ __forceinline__ uint32_t s2u(const void* p) {
    uint32_t a;
    asm("{ .reg .u64 t; cvta.to.shared.u64 t, %1; cvt.u32.u64 %0, t; }"
        : "=r"(a) : "l"(p));
    return a;
}

__device__ __forceinline__ void cp_async16(uint32_t dst, const void* src) {
    asm volatile("cp.async.cg.shared.global [%0], [%1], 16;"
                 :: "r"(dst), "l"(src) : "memory");
}

__device__ __forceinline__ void ldsm4(uint32_t r[4], uint32_t addr) {
    asm volatile("ldmatrix.sync.aligned.m8n8.x4.shared.b16 {%0,%1,%2,%3}, [%4];"
                 : "=r"(r[0]), "=r"(r[1]), "=r"(r[2]), "=r"(r[3]) : "r"(addr));
}

__device__ __forceinline__ void mma_f16(float d[4], uint32_t a0, uint32_t a1,
                                        uint32_t a2, uint32_t a3,
                                        uint32_t b0, uint32_t b1)
{
    asm volatile(
        "mma.sync.aligned.m16n8k16.row.col.f32.f16.f16.f32 "
        "{%0,%1,%2,%3}, {%4,%5,%6,%7}, {%8,%9}, {%0,%1,%2,%3};"
        : "+f"(d[0]), "+f"(d[1]), "+f"(d[2]), "+f"(d[3])
        : "r"(a0), "r"(a1), "r"(a2), "r"(a3), "r"(b0), "r"(b1));
}

__device__ __forceinline__ void spin_flag(int* flags, int idx, int target) {
    while (*((volatile int*)&flags[idx]) < target) __nanosleep(64);
}

// ---------------------------------------------------------------------------
// Combined prep kernel (one launch)
// ---------------------------------------------------------------------------
__global__ void prep_all(const float* __restrict__ x,
                         const float* __restrict__ Wqkv,
                         const float* __restrict__ Wproj,
                         __half* __restrict__ xp,
                         __half* __restrict__ wtq,
                         __half* __restrict__ wtp)
{
    const int bid = blockIdx.x;
    const int tid = threadIdx.x;
    if (bid == 0 && tid < 64) {
        if (tid < 32) g_fq[tid] = 0;
        else          g_fy[tid - 32] = 0;
    }
    if (bid < 4096) {
        int i = bid * 256 + tid;
        float4 v = ((const float4*)x)[i];
        uint2 o;
        o.x = pack_h2(v.x, v.y);
        o.y = pack_h2(v.z, v.w);
        ((uint2*)xp)[i] = o;
        return;
    }
    __shared__ float t[32][33];
    const float* in;
    __half* out;
    int R, C, bx, by;
    if (bid < 4096 + 3072) {
        int tb = bid - 4096;
        in = Wqkv; out = wtq; R = CC; C = N_QKV;
        bx = tb % 96; by = tb / 96;
    } else {
        int tb = bid - 4096 - 3072;
        in = Wproj; out = wtp; R = CC; C = CC;
        bx = tb & 31; by = tb >> 5;
    }
    int xx = tid & 31, yy = tid >> 5;
    int c0 = bx * 32, r0 = by * 32;
#pragma unroll
    for (int i = 0; i < 32; i += 8)
        t[yy + i][xx] = in[(size_t)(r0 + yy + i) * C + c0 + xx];
    __syncthreads();
#pragma unroll
    for (int i = 0; i < 32; i += 8)
        out[(size_t)(c0 + yy + i) * R + r0 + xx] = __float2half_rn(t[xx][yy + i]);
}

// ---------------------------------------------------------------------------
// GEMM tiling: CTA 128x128, K-block 64 (fp16), 3-stage cp.async, 2 CTAs/SM.
// ---------------------------------------------------------------------------
#define GSTAGES 3
#define KB      64
#define HSTR    72
#define TILEH   (128*HSTR)
#define TILE_B  (TILEH*2)
#define GEMM_SMEM (GSTAGES*2*TILE_B)

#define AT_STR  72
#define AT_BUF  (64*AT_STR*2)

__device__ __forceinline__ void g_load_stage(uint32_t sbase, int s,
                                             const __half* Ag, const __half* Bg,
                                             int k0, int tid)
{
    uint32_t base = sbase + (uint32_t)s * 2 * TILE_B;
#pragma unroll
    for (int i = 0; i < 8; i++) {
        int f = tid + i * 128;
        int row = f >> 3, c = f & 7;
        cp_async16(base + row * (HSTR * 2) + c * 16,
                   Ag + (size_t)row * CC + k0 + c * 8);
        cp_async16(base + TILE_B + row * (HSTR * 2) + c * 16,
                   Bg + (size_t)row * CC + k0 + c * 8);
    }
    asm volatile("cp.async.commit_group;" ::: "memory");
}

__device__ __forceinline__ void gemm_mainloop(uint32_t sbase,
                                              const __half* Ag, const __half* Bg,
                                              int tid, int wm, int wn, int lane,
                                              float acc[4][8][4])
{
    const int aRow = wm * 64 + (lane & 15);
    const int aCol = ((lane >> 4) & 1) * 8;
    const int bRow = wn * 64 + ((lane >> 4) << 3) + (lane & 7);
    const int bCol = ((lane >> 3) & 1) * 8;

    const int NIT = CC / KB;   // 16
#pragma unroll
    for (int s = 0; s < GSTAGES - 1; s++)
        g_load_stage(sbase, s, Ag, Bg, s * KB, tid);

    for (int it = 0; it < NIT; it++) {
        if (it < NIT - 1)
            asm volatile("cp.async.wait_group %0;" :: "n"(GSTAGES - 2) : "memory");
        else
            asm volatile("cp.async.wait_group 0;" ::: "memory");
        __syncthreads();

        if (it + GSTAGES - 1 < NIT)
            g_load_stage(sbase, (it + GSTAGES - 1) % GSTAGES, Ag, Bg,
                         (it + GSTAGES - 1) * KB, tid);

        const uint32_t Aab = sbase + (uint32_t)(it % GSTAGES) * 2 * TILE_B;
        const uint32_t Bab = Aab + TILE_B;

#pragma unroll
        for (int h = 0; h < 4; h++) {
            uint32_t au[4][4];
#pragma unroll
            for (int mt = 0; mt < 4; mt++)
                ldsm4(au[mt], Aab + (uint32_t)(((aRow + mt * 16) * HSTR
                                                + h * 16 + aCol) * 2));
            uint32_t bu[4][4];
#pragma unroll
            for (int p = 0; p < 4; p++)
                ldsm4(bu[p], Bab + (uint32_t)(((bRow + p * 16) * HSTR
                                               + h * 16 + bCol) * 2));
#pragma unroll
            for (int mt = 0; mt < 4; mt++)
#pragma unroll
                for (int nt = 0; nt < 8; nt++)
                    mma_f16(acc[mt][nt], au[mt][0], au[mt][1], au[mt][2],
                            au[mt][3], bu[nt >> 1][(nt & 1) * 2],
                            bu[nt >> 1][(nt & 1) * 2 + 1]);
        }
    }
}

// ---------------------------------------------------------------------------
// Mega-kernel:
//   bids    0.. 767 : QKV GEMM, DESCENDING-t m-blocks (release g_fq)
//   bids  768..1791 : flash attention, DESCENDING k-tiles (g_fq -> g_fy)
//   bids 1792..2047 : proj GEMM heavy-first (consume g_fy)
// ---------------------------------------------------------------------------
__global__ __launch_bounds__(128, 2)
void mega_kernel(const __half* __restrict__ A, const __half* __restrict__ Bt,
                 const float* __restrict__ bias, __half* __restrict__ Yg,
                 const __half* __restrict__ Wp, const float* __restrict__ bp,
                 float* __restrict__ Out)
{
    extern __shared__ __align__(16) __half smh[];
    const uint32_t sbase = s2u(smh);
    const int tid = threadIdx.x;
    const int bid = blockIdx.x;
    const int lane = tid & 31;
    const int r    = lane >> 2;
    const int l4   = lane & 3;

    if (bid < 768) {
        // ================= QKV GEMM (descending-t production) ==============
        const int wid = tid >> 5;
        const int wm  = wid & 1;
        const int wn  = wid >> 1;
        const int rank = bid / 24, nblk = bid % 24;
        const int mblock = ((rank & 1) << 4) | (15 - (rank >> 1));
        const int m0 = mblock << 7, n0 = nblk << 7;

        float acc[4][8][4];
#pragma unroll
        for (int mt = 0; mt < 4; mt++)
#pragma unroll
            for (int nt = 0; nt < 8; nt++)
#pragma unroll
                for (int j = 0; j < 4; j++) acc[mt][nt][j] = 0.0f;

        gemm_mainloop(sbase, A + (size_t)m0 * CC, Bt + (size_t)n0 * CC,
                      tid, wm, wn, lane, acc);

        const float QS = 0.125f * 1.44269504089f;
#pragma unroll
        for (int mt = 0; mt < 4; mt++) {
#pragma unroll
            for (int nt = 0; nt < 8; nt++) {
                const int row = m0 + wm * 64 + mt * 16 + r;
                const int c   = n0 + wn * 64 + nt * 8 + 2 * l4;
                const float b0v = __ldg(bias + c);
                const float b1v = __ldg(bias + c + 1);
                float v00 = acc[mt][nt][0] + b0v, v01 = acc[mt][nt][1] + b1v;
                float v10 = acc[mt][nt][2] + b0v, v11 = acc[mt][nt][3] + b1v;
                const int sec = c >> 10;
                const int cs = c & 1023, h = cs >> 6, d0 = cs & 63;
                const int b  = row >> 11;
                const int t0 = row & 2047;
                const int t1 = (row + 8) & 2047;
                if (sec == 2) {
                    __half* vb = g_v + ((size_t)(b * HH + h) * HD) * TT;
                    vb[(size_t)d0 * TT + t0]       = __float2half_rn(v00);
                    vb[(size_t)(d0 + 1) * TT + t0] = __float2half_rn(v01);
                    vb[(size_t)d0 * TT + t1]       = __float2half_rn(v10);
                    vb[(size_t)(d0 + 1) * TT + t1] = __float2half_rn(v11);
                } else {
                    if (sec == 0) { v00 *= QS; v01 *= QS; v10 *= QS; v11 *= QS; }
                    __half* basep = (sec == 0) ? g_q : g_k;
                    __half* p0 = basep + (((size_t)(b * HH + h) * TT + t0) * HD + d0);
                    __half* p1 = basep + (((size_t)(b * HH + h) * TT + t1) * HD + d0);
                    *(uint32_t*)p0 = pack_h2(v00, v01);
                    *(uint32_t*)p1 = pack_h2(v10, v11);
                }
            }
        }
        __syncthreads();
        __threadfence();
        if (tid == 0) atomicAdd(&g_fq[mblock], 1);
        return;
    }

    if (bid >= 1792) {
        // ================= Proj GEMM (consumes g_fy, heavy-first) ===========
        const int pbid = bid - 1792;
        const int wid = tid >> 5;
        const int wm  = wid & 1;
        const int wn  = wid >> 1;
        const int rank = pbid >> 3, nblk = pbid & 7;
        const int mb_w = 15 - (rank >> 1);
        const int b    = rank & 1;
        const int mblock = b * 16 + mb_w;
        const int m0 = mblock << 7, n0 = nblk << 7;

        if (tid == 0) {
            spin_flag(g_fy, mblock, 32);
            __threadfence();
        }
        __syncthreads();

        float acc[4][8][4];
#pragma unroll
        for (int mt = 0; mt < 4; mt++)
#pragma unroll
            for (int nt = 0; nt < 8; nt++)
#pragma unroll
                for (int j = 0; j < 4; j++) acc[mt][nt][j] = 0.0f;

        gemm_mainloop(sbase, Yg + (size_t)m0 * CC, Wp + (size_t)n0 * CC,
                      tid, wm, wn, lane, acc);

#pragma unroll
        for (int mt = 0; mt < 4; mt++) {
#pragma unroll
            for (int nt = 0; nt < 8; nt++) {
                const int row = m0 + wm * 64 + mt * 16 + r;
                const int c   = n0 + wn * 64 + nt * 8 + 2 * l4;
                const float b0v = __ldg(bp + c);
                const float b1v = __ldg(bp + c + 1);
                *(float2*)(Out + (size_t)row * CC + c)
                    = make_float2(acc[mt][nt][0] + b0v, acc[mt][nt][1] + b1v);
                *(float2*)(Out + (size_t)(row + 8) * CC + c)
                    = make_float2(acc[mt][nt][2] + b0v, acc[mt][nt][3] + b1v);
            }
        }
        return;
    }

    // ======= Flash attention (q-tile 64, 4 warps, DESCENDING k-tiles) ======
    {
        const int abid = bid - 768;
        const int qb   = 31 - (abid >> 5);          // heavy-first
        const int bh   = abid & 31;
        const int b    = bh >> 4, h = bh & 15;
        const int qbase = qb * 64;
        const int bqoff  = b * 16;
        const int w = tid >> 5;

        const uint32_t koff = (uint32_t)AT_BUF;
        const uint32_t PS_B = (uint32_t)(4 * 64 * AT_STR * 2);

        const __half* Qp  = g_q + (size_t)bh * TT * HD;
        const __half* Kp  = g_k + (size_t)bh * TT * HD;
        const __half* Vtp = g_v + (size_t)bh * HD * TT;

        // Q block == first K/V tile's block (descending iteration starts at qb)
        if (tid == 0) {
            spin_flag(g_fq, bqoff + (qb >> 1), 24);
            if (qb >= 1) spin_flag(g_fq, bqoff + ((qb - 1) >> 1), 24);
            __threadfence();
        }
        __syncthreads();

        // Q (64x64) into Ps; K/V tile kt0=qb into buffer (qb & 1)
        {
            const int kb0 = qbase;
            const uint32_t buf0 = (uint32_t)(qb & 1);
#pragma unroll
            for (int i = 0; i < 4; i++) {
                int f = tid + i * 128;
                int row = f >> 3, c = f & 7;
                cp_async16(sbase + PS_B + (uint32_t)(row * AT_STR) * 2 + c * 16,
                           Qp + (size_t)(qbase + row) * HD + c * 8);
                cp_async16(sbase + buf0 * koff + (uint32_t)(row * AT_STR) * 2 + c * 16,
                           Kp + (size_t)(kb0 + row) * HD + c * 8);
                cp_async16(sbase + 2 * koff + buf0 * koff
                           + (uint32_t)(row * AT_STR) * 2 + c * 16,
                           Vtp + (size_t)row * TT + kb0 + c * 8);
            }
        }
        asm volatile("cp.async.commit_group;" ::: "memory");
        asm volatile("cp.async.wait_group 0;" ::: "memory");
        __syncthreads();

        const int aRowL = lane & 15;
        const int aColL = ((lane >> 4) & 1) * 8;
        const int bRowL = ((lane >> 4) << 3) + (lane & 7);
        const int bColL = ((lane >> 3) & 1) * 8;

        uint32_t aq[4][4];
#pragma unroll
        for (int hc = 0; hc < 4; hc++)
            ldsm4(aq[hc], sbase + PS_B +
                  (uint32_t)(((w * 16 + aRowL) * AT_STR + hc * 16 + aColL) * 2));
        __syncthreads();   // Ps now free for P

        float O[8][4];
#pragma unroll
        for (int nt = 0; nt < 8; nt++)
#pragma unroll
            for (int j = 0; j < 4; j++) O[nt][j] = 0.0f;
        float m0v = -1e30f, m1v = -1e30f, l0v = 0.0f, l1v = 0.0f;

        const int tq0 = qbase + w * 16 + r;
        const int tq1 = tq0 + 8;
        __half* pw = smh + 4 * 64 * AT_STR + (w * 16) * AT_STR;
        const uint32_t pwAddr = sbase + PS_B + (uint32_t)(w * 16 * AT_STR * 2);

        for (int kt = qb; kt >= 0; kt--) {
            const int kbase = kt * 64;
            const int buf = kt & 1;
            const uint32_t kAddr = sbase + (uint32_t)buf * koff;
            const uint32_t vAddr = sbase + 2 * koff + (uint32_t)buf * koff;
            const bool more = (kt > 0);

            if (more) {
                const int nb = kbase - 64;
                uint32_t kd = sbase + (uint32_t)(buf ^ 1) * koff;
                uint32_t vd = sbase + 2 * koff + (uint32_t)(buf ^ 1) * koff;
#pragma unroll
                for (int i = 0; i < 4; i++) {
                    int f = tid + i * 128;
                    int row = f >> 3, c = f & 7;
                    cp_async16(kd + (uint32_t)(row * AT_STR) * 2 + c * 16,
                               Kp + (size_t)(nb + row) * HD + c * 8);
                    cp_async16(vd + (uint32_t)(row * AT_STR) * 2 + c * 16,
                               Vtp + (size_t)row * TT + nb + c * 8);
                }
                asm volatile("cp.async.commit_group;" ::: "memory");
            }

            // S = Q K^T
            float s[8][4];
#pragma unroll
            for (int nt = 0; nt < 8; nt++)
#pragma unroll
                for (int j = 0; j < 4; j++) s[nt][j] = 0.0f;
#pragma unroll
            for (int hc = 0; hc < 4; hc++) {
                uint32_t ku[4][4];
#pragma unroll
                for (int p = 0; p < 4; p++)
                    ldsm4(ku[p], kAddr + (uint32_t)(((p * 16 + bRowL) * AT_STR
                                                    + hc * 16 + bColL) * 2));
#pragma unroll
                for (int nt = 0; nt < 8; nt++)
                    mma_f16(s[nt], aq[hc][0], aq[hc][1], aq[hc][2], aq[hc][3],
                            ku[nt >> 1][(nt & 1) * 2],
                            ku[nt >> 1][(nt & 1) * 2 + 1]);
            }

            // causal mask (diagonal tile only; processed FIRST now)
            if (kbase + 63 > qbase + w * 16) {
#pragma unroll
                for (int nt = 0; nt < 8; nt++) {
                    int tk = kbase + nt * 8 + 2 * l4;
                    if (tk     > tq0) s[nt][0] = -1e30f;
                    if (tk + 1 > tq0) s[nt][1] = -1e30f;
                    if (tk     > tq1) s[nt][2] = -1e30f;
                    if (tk + 1 > tq1) s[nt][3] = -1e30f;
                }
            }

            // online softmax (log2 domain) — order-invariant
            float ml0 = -1e30f, ml1 = -1e30f;
#pragma unroll
            for (int nt = 0; nt < 8; nt++) {
                ml0 = fmaxf(ml0, fmaxf(s[nt][0], s[nt][1]));
                ml1 = fmaxf(ml1, fmaxf(s[nt][2], s[nt][3]));
            }
            ml0 = fmaxf(ml0, __shfl_xor_sync(0xffffffffu, ml0, 1));
            ml0 = fmaxf(ml0, __shfl_xor_sync(0xffffffffu, ml0, 2));
            ml1 = fmaxf(ml1, __shfl_xor_sync(0xffffffffu, ml1, 1));
            ml1 = fmaxf(ml1, __shfl_xor_sync(0xffffffffu, ml1, 2));
            float mn0 = fmaxf(m0v, ml0), mn1 = fmaxf(m1v, ml1);
            float c0 = ex2(m0v - mn0), c1 = ex2(m1v - mn1);
            float ps0 = 0.0f, ps1 = 0.0f;
#pragma unroll
            for (int nt = 0; nt < 8; nt++) {
                s[nt][0] = ex2(s[nt][0] - mn0); ps0 += s[nt][0];
                s[nt][1] = ex2(s[nt][1] - mn0); ps0 += s[nt][1];
                s[nt][2] = ex2(s[nt][2] - mn1); ps1 += s[nt][2];
                s[nt][3] = ex2(s[nt][3] - mn1); ps1 += s[nt][3];
            }
            ps0 += __shfl_xor_sync(0xffffffffu, ps0, 1);
            ps0 += __shfl_xor_sync(0xffffffffu, ps0, 2);
            ps1 += __shfl_xor_sync(0xffffffffu, ps1, 1);
            ps1 += __shfl_xor_sync(0xffffffffu, ps1, 2);
            l0v = l0v * c0 + ps0; m0v = mn0;
            l1v = l1v * c1 + ps1; m1v = mn1;
#pragma unroll
            for (int nt = 0; nt < 8; nt++) {
                O[nt][0] *= c0; O[nt][1] *= c0;
                O[nt][2] *= c1; O[nt][3] *= c1;
            }

            // P -> per-warp smem as half2
#pragma unroll
            for (int nt = 0; nt < 8; nt++) {
                *(uint32_t*)(pw + r * AT_STR + nt * 8 + 2 * l4)
                    = pack_h2(s[nt][0], s[nt][1]);
                *(uint32_t*)(pw + (r + 8) * AT_STR + nt * 8 + 2 * l4)
                    = pack_h2(s[nt][2], s[nt][3]);
            }
            __syncwarp();

            // O += P V
#pragma unroll
            for (int hc = 0; hc < 4; hc++) {
                uint32_t pa[4];
                ldsm4(pa, pwAddr + (uint32_t)((aRowL * AT_STR
                                               + hc * 16 + aColL) * 2));
                uint32_t vu[4][4];
#pragma unroll
                for (int p = 0; p < 4; p++)
                    ldsm4(vu[p], vAddr + (uint32_t)(((p * 16 + bRowL) * AT_STR
                                                    + hc * 16 + bColL) * 2));
#pragma unroll
                for (int nt = 0; nt < 8; nt++)
                    mma_f16(O[nt], pa[0], pa[1], pa[2], pa[3],
                            vu[nt >> 1][(nt & 1) * 2],
                            vu[nt >> 1][(nt & 1) * 2 + 1]);
            }

            if (more) {
                asm volatile("cp.async.wait_group 0;" ::: "memory");
                if (tid == 0) {
                    if (kt - 2 >= 0) spin_flag(g_fq, bqoff + ((kt - 2) >> 1), 24);
                    __threadfence();
                }
                __syncthreads();
            }
        }

        // Epilogue: normalize, half y, release g_fy
        const int hb = h * 64;
        const float inv0 = 1.0f / l0v, inv1 = 1.0f / l1v;
        __half* y0 = Yg + (size_t)(b * TT + tq0) * CC;
        __half* y1 = Yg + (size_t)(b * TT + tq1) * CC;
#pragma unroll
        for (int nt = 0; nt < 8; nt++) {
            int c = hb + nt * 8 + 2 * l4;
            *(uint32_t*)(y0 + c) = pack_h2(O[nt][0] * inv0, O[nt][1] * inv0);
            *(uint32_t*)(y1 + c) = pack_h2(O[nt][2] * inv1, O[nt][3] * inv1);
        }
        __syncthreads();
        __threadfence();
        if (tid == 0) atomicAdd(&g_fy[b * 16 + (qb >> 1)], 1);
    }
}

// ---------------------------------------------------------------------------
// Launch
// ---------------------------------------------------------------------------
extern "C" void kernel_launch(void* const* d_in, const int* in_sizes, int n_in,
                              void* d_out, int out_size)
{
    const float* x     = (const float*)d_in[0];
    const float* Wqkv  = (const float*)d_in[1];
    const float* bqkv  = (const float*)d_in[2];
    const float* Wproj = (const float*)d_in[3];
    const float* bproj = (const float*)d_in[4];
    float* out = (float*)d_out;
    (void)in_sizes; (void)n_in; (void)out_size;

    __half *yp, *xp, *wtq, *wtp;
    cudaGetSymbolAddress((void**)&yp,  g_y);
    cudaGetSymbolAddress((void**)&xp,  g_xp);
    cudaGetSymbolAddress((void**)&wtq, g_wtq);
    cudaGetSymbolAddress((void**)&wtp, g_wtp);

    cudaFuncSetAttribute(mega_kernel, cudaFuncAttributeMaxDynamicSharedMemorySize, GEMM_SMEM);

    prep_all<<<4096 + 3072 + 1024, 256>>>(x, Wqkv, Wproj, xp, wtq, wtp);

    mega_kernel<<<768 + 1024 + 256, 128, GEMM_SMEM>>>(xp, wtq, bqkv, yp,
                                                      wtp, bproj, out);
}